// round 2
// baseline (speedup 1.0000x reference)
#include <cuda_runtime.h>
#include <cstdint>

#define N_NODES 16384
#define KNB 48
#define CV 128
#define IN_DIM 384
#define DW 512
#define LN_EPS 1e-5f

#define WS_STR 130   // double units, stride for 128-wide W tile (pad: 130*8 % 16 == 0)
#define Y_STR 132    // float units, stride for activation tiles

typedef unsigned long long u64;

// ---------- helpers ----------

__device__ __forceinline__ u64 ffma2(u64 a, u64 b, u64 c) {
    u64 d;
    asm("fma.rn.f32x2 %0, %1, %2, %3;" : "=l"(d) : "l"(a), "l"(b), "l"(c));
    return d;
}

__device__ __forceinline__ float unpack_sum(u64 a) {
    float lo = __uint_as_float((unsigned)(a & 0xffffffffull));
    float hi = __uint_as_float((unsigned)(a >> 32));
    return lo + hi;
}

__device__ __forceinline__ float gelu_f(float x) {
    // exact gelu (approximate=False): 0.5*x*(1+erf(x/sqrt(2)))
    return 0.5f * x * (1.0f + erff(x * 0.70710678118654752f));
}

// ---------- scratch (allocation-free) ----------
__device__ float g_dh[N_NODES * CV];   // summed messages / 30
__device__ float g_v1[N_NODES * CV];   // h_V after LN1
__device__ float g_yd[(size_t)N_NODES * DW]; // dense hidden

// ============================================================
// Kernel 1: message MLP (IN=384 -> 128 -> 128 -> 128), fused
// mask_attend multiply and sum over K -> g_dh.
// Block = 2 nodes = 96 edge rows. 256 threads, 6x8 microtile (f32x2 packed).
// ============================================================
#define MSG_XSTR 98  // double units (96 rows + pad), 98*8 % 16 == 0

__global__ void __launch_bounds__(256, 1)
k_msg(const float* __restrict__ hV, const float* __restrict__ hE,
      const int* __restrict__ nbr, const float* __restrict__ maskA,
      const float* __restrict__ w1, const float* __restrict__ b1,
      const float* __restrict__ w2, const float* __restrict__ b2,
      const float* __restrict__ w3, const float* __restrict__ b3)
{
    extern __shared__ char smem_raw[];
    double* XsD = (double*)smem_raw;            // [16][MSG_XSTR]
    double* WsD = XsD + 16 * MSG_XSTR;          // [16][WS_STR]
    float*  Y1  = (float*)(WsD + 16 * WS_STR);  // [96][Y_STR]
    float*  Y2  = Y1 + 96 * Y_STR;              // [96][Y_STR]

    const int tid = threadIdx.x;
    const int tx = tid & 15;   // col group: cols tx*8..tx*8+7
    const int ty = tid >> 4;   // row group: rows ty*6..ty*6+5
    const int n0 = blockIdx.x * 2;

    u64 acc[6][8];
    #pragma unroll
    for (int i = 0; i < 6; i++)
        #pragma unroll
        for (int j = 0; j < 8; j++) acc[i][j] = 0ull;

    // ---------------- layer 1: K = 384 ----------------
    for (int kt = 0; kt < IN_DIM; kt += 32) {
        __syncthreads();
        // stage X (concat [hV_self | hE | hV_nbr]) as k-pairs
        for (int e = tid; e < 96 * 16; e += 256) {
            int r = e >> 4, kk2 = e & 15;
            int node = n0 + (r >= 48);
            int k = (r < 48) ? r : (r - 48);
            int c = kt + 2 * kk2;
            float2 val;
            if (c < CV) {
                val = *(const float2*)&hV[node * CV + c];
            } else if (c < 2 * CV) {
                val = *(const float2*)&hE[(node * KNB + k) * CV + (c - CV)];
            } else {
                int nb = nbr[node * KNB + k];
                val = *(const float2*)&hV[nb * CV + (c - 2 * CV)];
            }
            *(float2*)&XsD[kk2 * MSG_XSTR + r] = val;
        }
        // stage W1 tile (w[o][i], k-pairs)
        for (int e = tid; e < 128 * 16; e += 256) {
            int c = e >> 4, kk2 = e & 15;
            *(float2*)&WsD[kk2 * WS_STR + c] = *(const float2*)&w1[c * IN_DIM + kt + 2 * kk2];
        }
        __syncthreads();
        #pragma unroll
        for (int kk2 = 0; kk2 < 16; ++kk2) {
            const double2* xp = (const double2*)(XsD + kk2 * MSG_XSTR + ty * 6);
            double2 xa = xp[0], xb = xp[1], xc = xp[2];
            u64 xf[6] = { (u64)__double_as_longlong(xa.x), (u64)__double_as_longlong(xa.y),
                          (u64)__double_as_longlong(xb.x), (u64)__double_as_longlong(xb.y),
                          (u64)__double_as_longlong(xc.x), (u64)__double_as_longlong(xc.y) };
            const double2* wp = (const double2*)(WsD + kk2 * WS_STR + tx * 8);
            double2 wa = wp[0], wb = wp[1], wc = wp[2], wd = wp[3];
            u64 wf[8] = { (u64)__double_as_longlong(wa.x), (u64)__double_as_longlong(wa.y),
                          (u64)__double_as_longlong(wb.x), (u64)__double_as_longlong(wb.y),
                          (u64)__double_as_longlong(wc.x), (u64)__double_as_longlong(wc.y),
                          (u64)__double_as_longlong(wd.x), (u64)__double_as_longlong(wd.y) };
            #pragma unroll
            for (int i = 0; i < 6; i++)
                #pragma unroll
                for (int j = 0; j < 8; j++)
                    acc[i][j] = ffma2(xf[i], wf[j], acc[i][j]);
        }
    }
    // epilogue 1: bias + gelu -> Y1
    {
        float bb[8];
        #pragma unroll
        for (int j = 0; j < 8; j++) bb[j] = b1[tx * 8 + j];
        #pragma unroll
        for (int i = 0; i < 6; i++)
            #pragma unroll
            for (int j = 0; j < 8; j++) {
                float v = unpack_sum(acc[i][j]) + bb[j];
                Y1[(ty * 6 + i) * Y_STR + tx * 8 + j] = gelu_f(v);
            }
    }

    // ---------------- layer 2: K = 128 (input Y1) ----------------
    #pragma unroll
    for (int i = 0; i < 6; i++)
        #pragma unroll
        for (int j = 0; j < 8; j++) acc[i][j] = 0ull;
    for (int kt = 0; kt < CV; kt += 32) {
        __syncthreads();
        for (int e = tid; e < 128 * 16; e += 256) {
            int c = e >> 4, kk2 = e & 15;
            *(float2*)&WsD[kk2 * WS_STR + c] = *(const float2*)&w2[c * CV + kt + 2 * kk2];
        }
        __syncthreads();
        #pragma unroll
        for (int kk2 = 0; kk2 < 16; ++kk2) {
            u64 xf[6];
            #pragma unroll
            for (int i = 0; i < 6; i++)
                xf[i] = *(const u64*)&Y1[(ty * 6 + i) * Y_STR + kt + 2 * kk2];
            const double2* wp = (const double2*)(WsD + kk2 * WS_STR + tx * 8);
            double2 wa = wp[0], wb = wp[1], wc = wp[2], wd = wp[3];
            u64 wf[8] = { (u64)__double_as_longlong(wa.x), (u64)__double_as_longlong(wa.y),
                          (u64)__double_as_longlong(wb.x), (u64)__double_as_longlong(wb.y),
                          (u64)__double_as_longlong(wc.x), (u64)__double_as_longlong(wc.y),
                          (u64)__double_as_longlong(wd.x), (u64)__double_as_longlong(wd.y) };
            #pragma unroll
            for (int i = 0; i < 6; i++)
                #pragma unroll
                for (int j = 0; j < 8; j++)
                    acc[i][j] = ffma2(xf[i], wf[j], acc[i][j]);
        }
    }
    // epilogue 2: bias + gelu -> Y2
    {
        float bb[8];
        #pragma unroll
        for (int j = 0; j < 8; j++) bb[j] = b2[tx * 8 + j];
        #pragma unroll
        for (int i = 0; i < 6; i++)
            #pragma unroll
            for (int j = 0; j < 8; j++) {
                float v = unpack_sum(acc[i][j]) + bb[j];
                Y2[(ty * 6 + i) * Y_STR + tx * 8 + j] = gelu_f(v);
            }
    }

    // ---------------- layer 3: K = 128 (input Y2) ----------------
    #pragma unroll
    for (int i = 0; i < 6; i++)
        #pragma unroll
        for (int j = 0; j < 8; j++) acc[i][j] = 0ull;
    for (int kt = 0; kt < CV; kt += 32) {
        __syncthreads();
        for (int e = tid; e < 128 * 16; e += 256) {
            int c = e >> 4, kk2 = e & 15;
            *(float2*)&WsD[kk2 * WS_STR + c] = *(const float2*)&w3[c * CV + kt + 2 * kk2];
        }
        __syncthreads();
        #pragma unroll
        for (int kk2 = 0; kk2 < 16; ++kk2) {
            u64 xf[6];
            #pragma unroll
            for (int i = 0; i < 6; i++)
                xf[i] = *(const u64*)&Y2[(ty * 6 + i) * Y_STR + kt + 2 * kk2];
            const double2* wp = (const double2*)(WsD + kk2 * WS_STR + tx * 8);
            double2 wa = wp[0], wb = wp[1], wc = wp[2], wd = wp[3];
            u64 wf[8] = { (u64)__double_as_longlong(wa.x), (u64)__double_as_longlong(wa.y),
                          (u64)__double_as_longlong(wb.x), (u64)__double_as_longlong(wb.y),
                          (u64)__double_as_longlong(wc.x), (u64)__double_as_longlong(wc.y),
                          (u64)__double_as_longlong(wd.x), (u64)__double_as_longlong(wd.y) };
            #pragma unroll
            for (int i = 0; i < 6; i++)
                #pragma unroll
                for (int j = 0; j < 8; j++)
                    acc[i][j] = ffma2(xf[i], wf[j], acc[i][j]);
        }
    }
    // epilogue 3: bias, mask_attend, store m -> Y1, reduce over K
    {
        float bb[8];
        #pragma unroll
        for (int j = 0; j < 8; j++) bb[j] = b3[tx * 8 + j];
        #pragma unroll
        for (int i = 0; i < 6; i++) {
            int r = ty * 6 + i;
            float ma = maskA[n0 * KNB + r];
            #pragma unroll
            for (int j = 0; j < 8; j++)
                Y1[r * Y_STR + tx * 8 + j] = (unpack_sum(acc[i][j]) + bb[j]) * ma;
        }
    }
    __syncthreads();
    {
        int a = tid >> 7, c = tid & 127;
        float s = 0.f;
        #pragma unroll
        for (int k = 0; k < KNB; k++) s += Y1[(a * KNB + k) * Y_STR + c];
        g_dh[(n0 + a) * CV + c] = s * (1.0f / 30.0f);
    }
}

// ============================================================
// Kernel 2: v1 = LN1(h_V + dh)
// ============================================================
__global__ void k_ln1(const float* __restrict__ hV,
                      const float* __restrict__ w, const float* __restrict__ b)
{
    int n = blockIdx.x, t = threadIdx.x;
    float x = hV[n * CV + t] + g_dh[n * CV + t];
    float s = x, sq = x * x;
    #pragma unroll
    for (int o = 16; o > 0; o >>= 1) {
        s  += __shfl_xor_sync(0xffffffffu, s, o);
        sq += __shfl_xor_sync(0xffffffffu, sq, o);
    }
    __shared__ float ss[4], ssq[4];
    int wid = t >> 5, lane = t & 31;
    if (lane == 0) { ss[wid] = s; ssq[wid] = sq; }
    __syncthreads();
    s  = ss[0] + ss[1] + ss[2] + ss[3];
    sq = ssq[0] + ssq[1] + ssq[2] + ssq[3];
    float mean = s * (1.0f / CV);
    float var  = sq * (1.0f / CV) - mean * mean;
    float inv  = rsqrtf(var + LN_EPS);
    g_v1[n * CV + t] = (x - mean) * inv * w[t] + b[t];
}

// ============================================================
// Kernel 3: dense hidden  g_yd = gelu(v1 @ d_w1^T + b1)  [16384,512]
// block tile: 64 rows x 128 cols, K=128, 4x8 microtile
// ============================================================
#define D_XSTR 66

__global__ void __launch_bounds__(256, 1)
k_dense1(const float* __restrict__ w, const float* __restrict__ b)
{
    extern __shared__ char smem_raw[];
    double* XsD = (double*)smem_raw;     // [16][D_XSTR]
    double* WsD = XsD + 16 * D_XSTR;     // [16][WS_STR]
    int tid = threadIdx.x, tx = tid & 15, ty = tid >> 4;
    int r0 = blockIdx.x * 64, c0 = blockIdx.y * 128;

    u64 acc[4][8];
    #pragma unroll
    for (int i = 0; i < 4; i++)
        #pragma unroll
        for (int j = 0; j < 8; j++) acc[i][j] = 0ull;

    for (int kt = 0; kt < CV; kt += 32) {
        __syncthreads();
        for (int e = tid; e < 64 * 16; e += 256) {
            int r = e >> 4, kk2 = e & 15;
            *(float2*)&XsD[kk2 * D_XSTR + r] = *(const float2*)&g_v1[(r0 + r) * CV + kt + 2 * kk2];
        }
        for (int e = tid; e < 128 * 16; e += 256) {
            int c = e >> 4, kk2 = e & 15;
            *(float2*)&WsD[kk2 * WS_STR + c] = *(const float2*)&w[(c0 + c) * CV + kt + 2 * kk2];
        }
        __syncthreads();
        #pragma unroll
        for (int kk2 = 0; kk2 < 16; ++kk2) {
            const double2* xp = (const double2*)(XsD + kk2 * D_XSTR + ty * 4);
            double2 xa = xp[0], xb = xp[1];
            u64 xf[4] = { (u64)__double_as_longlong(xa.x), (u64)__double_as_longlong(xa.y),
                          (u64)__double_as_longlong(xb.x), (u64)__double_as_longlong(xb.y) };
            const double2* wp = (const double2*)(WsD + kk2 * WS_STR + tx * 8);
            double2 wa = wp[0], wb = wp[1], wc = wp[2], wd = wp[3];
            u64 wf[8] = { (u64)__double_as_longlong(wa.x), (u64)__double_as_longlong(wa.y),
                          (u64)__double_as_longlong(wb.x), (u64)__double_as_longlong(wb.y),
                          (u64)__double_as_longlong(wc.x), (u64)__double_as_longlong(wc.y),
                          (u64)__double_as_longlong(wd.x), (u64)__double_as_longlong(wd.y) };
            #pragma unroll
            for (int i = 0; i < 4; i++)
                #pragma unroll
                for (int j = 0; j < 8; j++)
                    acc[i][j] = ffma2(xf[i], wf[j], acc[i][j]);
        }
    }
    #pragma unroll
    for (int i = 0; i < 4; i++)
        #pragma unroll
        for (int j = 0; j < 8; j++) {
            int c = c0 + tx * 8 + j;
            float v = unpack_sum(acc[i][j]) + b[c];
            g_yd[(size_t)(r0 + ty * 4 + i) * DW + c] = gelu_f(v);
        }
}

// ============================================================
// Kernel 4: z = g_yd @ d_w2^T + b2 + v1; h_V = LN2(z) * mask -> d_out
// block tile: 64 rows x 128 cols (full row -> fused LN), K=512
// ============================================================
__global__ void __launch_bounds__(256, 1)
k_dense2(const float* __restrict__ w, const float* __restrict__ b,
         const float* __restrict__ lnw, const float* __restrict__ lnb,
         const float* __restrict__ mask, float* __restrict__ outV)
{
    extern __shared__ char smem_raw[];
    double* XsD = (double*)smem_raw;            // [16][D_XSTR]
    double* WsD = XsD + 16 * D_XSTR;            // [16][WS_STR]
    float*  Z   = (float*)(WsD + 16 * WS_STR);  // [64][Y_STR]
    int tid = threadIdx.x, tx = tid & 15, ty = tid >> 4;
    int r0 = blockIdx.x * 64;

    u64 acc[4][8];
    #pragma unroll
    for (int i = 0; i < 4; i++)
        #pragma unroll
        for (int j = 0; j < 8; j++) acc[i][j] = 0ull;

    for (int kt = 0; kt < DW; kt += 32) {
        __syncthreads();
        for (int e = tid; e < 64 * 16; e += 256) {
            int r = e >> 4, kk2 = e & 15;
            *(float2*)&XsD[kk2 * D_XSTR + r] = *(const float2*)&g_yd[(size_t)(r0 + r) * DW + kt + 2 * kk2];
        }
        for (int e = tid; e < 128 * 16; e += 256) {
            int c = e >> 4, kk2 = e & 15;
            *(float2*)&WsD[kk2 * WS_STR + c] = *(const float2*)&w[c * DW + kt + 2 * kk2];
        }
        __syncthreads();
        #pragma unroll
        for (int kk2 = 0; kk2 < 16; ++kk2) {
            const double2* xp = (const double2*)(XsD + kk2 * D_XSTR + ty * 4);
            double2 xa = xp[0], xb = xp[1];
            u64 xf[4] = { (u64)__double_as_longlong(xa.x), (u64)__double_as_longlong(xa.y),
                          (u64)__double_as_longlong(xb.x), (u64)__double_as_longlong(xb.y) };
            const double2* wp = (const double2*)(WsD + kk2 * WS_STR + tx * 8);
            double2 wa = wp[0], wb = wp[1], wc = wp[2], wd = wp[3];
            u64 wf[8] = { (u64)__double_as_longlong(wa.x), (u64)__double_as_longlong(wa.y),
                          (u64)__double_as_longlong(wb.x), (u64)__double_as_longlong(wb.y),
                          (u64)__double_as_longlong(wc.x), (u64)__double_as_longlong(wc.y),
                          (u64)__double_as_longlong(wd.x), (u64)__double_as_longlong(wd.y) };
            #pragma unroll
            for (int i = 0; i < 4; i++)
                #pragma unroll
                for (int j = 0; j < 8; j++)
                    acc[i][j] = ffma2(xf[i], wf[j], acc[i][j]);
        }
    }
    // residual + bias -> Z
    #pragma unroll
    for (int i = 0; i < 4; i++) {
        int r = ty * 4 + i;
        #pragma unroll
        for (int j = 0; j < 8; j++) {
            int c = tx * 8 + j;
            float v = unpack_sum(acc[i][j]) + b[c] + g_v1[(r0 + r) * CV + c];
            Z[r * Y_STR + c] = v;
        }
    }
    __syncthreads();
    // LN per row: 4 threads per row
    {
        int r = tid >> 2, q = tid & 3;
        float s = 0.f, sq = 0.f;
        #pragma unroll
        for (int c = q * 32; c < q * 32 + 32; c++) {
            float v = Z[r * Y_STR + c];
            s += v; sq += v * v;
        }
        s  += __shfl_xor_sync(0xffffffffu, s, 1);
        sq += __shfl_xor_sync(0xffffffffu, sq, 1);
        s  += __shfl_xor_sync(0xffffffffu, s, 2);
        sq += __shfl_xor_sync(0xffffffffu, sq, 2);
        float mean = s * (1.0f / CV);
        float var  = sq * (1.0f / CV) - mean * mean;
        float inv  = rsqrtf(var + LN_EPS);
        float mk = mask[r0 + r];
        for (int c = q * 32; c < q * 32 + 32; c++) {
            float v = Z[r * Y_STR + c];
            outV[(r0 + r) * CV + c] = ((v - mean) * inv * lnw[c] + lnb[c]) * mk;
        }
    }
}

// ============================================================
// Kernel 5: edge update MLP (384->128->128->128) + residual + LN3
// block = 128 edge rows, 8x8 microtile. Reads updated h_V from d_out.
// ============================================================
#define E_XSTR 130

__global__ void __launch_bounds__(256, 1)
k_edge(const float* __restrict__ hVnew, const float* __restrict__ hE,
       const int* __restrict__ nbr,
       const float* __restrict__ w1, const float* __restrict__ b1,
       const float* __restrict__ w2, const float* __restrict__ b2,
       const float* __restrict__ w3, const float* __restrict__ b3,
       const float* __restrict__ lnw, const float* __restrict__ lnb,
       float* __restrict__ outE)
{
    extern __shared__ char smem_raw[];
    double* XsD = (double*)smem_raw;            // [16][E_XSTR]
    double* WsD = XsD + 16 * E_XSTR;            // [16][WS_STR]
    float*  Y1  = (float*)(WsD + 16 * WS_STR);  // [128][Y_STR]
    float*  Y2  = Y1 + 128 * Y_STR;             // [128][Y_STR]

    const int tid = threadIdx.x;
    const int tx = tid & 15, ty = tid >> 4;
    const int e0 = blockIdx.x * 128;

    u64 acc[8][8];
    #pragma unroll
    for (int i = 0; i < 8; i++)
        #pragma unroll
        for (int j = 0; j < 8; j++) acc[i][j] = 0ull;

    // ---------------- layer 1: K = 384 ----------------
    for (int kt = 0; kt < IN_DIM; kt += 32) {
        __syncthreads();
        for (int e = tid; e < 128 * 16; e += 256) {
            int r = e >> 4, kk2 = e & 15;
            int eg = e0 + r;
            int node = eg / KNB;
            int c = kt + 2 * kk2;
            float2 val;
            if (c < CV) {
                val = *(const float2*)&hVnew[node * CV + c];
            } else if (c < 2 * CV) {
                val = *(const float2*)&hE[eg * CV + (c - CV)];
            } else {
                int nb = nbr[eg];
                val = *(const float2*)&hVnew[nb * CV + (c - 2 * CV)];
            }
            *(float2*)&XsD[kk2 * E_XSTR + r] = val;
        }
        for (int e = tid; e < 128 * 16; e += 256) {
            int c = e >> 4, kk2 = e & 15;
            *(float2*)&WsD[kk2 * WS_STR + c] = *(const float2*)&w1[c * IN_DIM + kt + 2 * kk2];
        }
        __syncthreads();
        #pragma unroll
        for (int kk2 = 0; kk2 < 16; ++kk2) {
            const double2* xp = (const double2*)(XsD + kk2 * E_XSTR + ty * 8);
            double2 xa = xp[0], xb = xp[1], xc = xp[2], xd = xp[3];
            u64 xf[8] = { (u64)__double_as_longlong(xa.x), (u64)__double_as_longlong(xa.y),
                          (u64)__double_as_longlong(xb.x), (u64)__double_as_longlong(xb.y),
                          (u64)__double_as_longlong(xc.x), (u64)__double_as_longlong(xc.y),
                          (u64)__double_as_longlong(xd.x), (u64)__double_as_longlong(xd.y) };
            const double2* wp = (const double2*)(WsD + kk2 * WS_STR + tx * 8);
            double2 wa = wp[0], wb = wp[1], wc = wp[2], wd = wp[3];
            u64 wf[8] = { (u64)__double_as_longlong(wa.x), (u64)__double_as_longlong(wa.y),
                          (u64)__double_as_longlong(wb.x), (u64)__double_as_longlong(wb.y),
                          (u64)__double_as_longlong(wc.x), (u64)__double_as_longlong(wc.y),
                          (u64)__double_as_longlong(wd.x), (u64)__double_as_longlong(wd.y) };
            #pragma unroll
            for (int i = 0; i < 8; i++)
                #pragma unroll
                for (int j = 0; j < 8; j++)
                    acc[i][j] = ffma2(xf[i], wf[j], acc[i][j]);
        }
    }
    {
        float bb[8];
        #pragma unroll
        for (int j = 0; j < 8; j++) bb[j] = b1[tx * 8 + j];
        #pragma unroll
        for (int i = 0; i < 8; i++)
            #pragma unroll
            for (int j = 0; j < 8; j++) {
                float v = unpack_sum(acc[i][j]) + bb[j];
                Y1[(ty * 8 + i) * Y_STR + tx * 8 + j] = gelu_f(v);
            }
    }

    // ---------------- layer 2: K = 128 ----------------
    #pragma unroll
    for (int i = 0; i < 8; i++)
        #pragma unroll
        for (int j = 0; j < 8; j++) acc[i][j] = 0ull;
    for (int kt = 0; kt < CV; kt += 32) {
        __syncthreads();
        for (int e = tid; e < 128 * 16; e += 256) {
            int c = e >> 4, kk2 = e & 15;
            *(float2*)&WsD[kk2 * WS_STR + c] = *(const float2*)&w2[c * CV + kt + 2 * kk2];
        }
        __syncthreads();
        #pragma unroll
        for (int kk2 = 0; kk2 < 16; ++kk2) {
            u64 xf[8];
            #pragma unroll
            for (int i = 0; i < 8; i++)
                xf[i] = *(const u64*)&Y1[(ty * 8 + i) * Y_STR + kt + 2 * kk2];
            const double2* wp = (const double2*)(WsD + kk2 * WS_STR + tx * 8);
            double2 wa = wp[0], wb = wp[1], wc = wp[2], wd = wp[3];
            u64 wf[8] = { (u64)__double_as_longlong(wa.x), (u64)__double_as_longlong(wa.y),
                          (u64)__double_as_longlong(wb.x), (u64)__double_as_longlong(wb.y),
                          (u64)__double_as_longlong(wc.x), (u64)__double_as_longlong(wc.y),
                          (u64)__double_as_longlong(wd.x), (u64)__double_as_longlong(wd.y) };
            #pragma unroll
            for (int i = 0; i < 8; i++)
                #pragma unroll
                for (int j = 0; j < 8; j++)
                    acc[i][j] = ffma2(xf[i], wf[j], acc[i][j]);
        }
    }
    {
        float bb[8];
        #pragma unroll
        for (int j = 0; j < 8; j++) bb[j] = b2[tx * 8 + j];
        #pragma unroll
        for (int i = 0; i < 8; i++)
            #pragma unroll
            for (int j = 0; j < 8; j++) {
                float v = unpack_sum(acc[i][j]) + bb[j];
                Y2[(ty * 8 + i) * Y_STR + tx * 8 + j] = gelu_f(v);
            }
    }

    // ---------------- layer 3: K = 128 ----------------
    #pragma unroll
    for (int i = 0; i < 8; i++)
        #pragma unroll
        for (int j = 0; j < 8; j++) acc[i][j] = 0ull;
    for (int kt = 0; kt < CV; kt += 32) {
        __syncthreads();
        for (int e = tid; e < 128 * 16; e += 256) {
            int c = e >> 4, kk2 = e & 15;
            *(float2*)&WsD[kk2 * WS_STR + c] = *(const float2*)&w3[c * CV + kt + 2 * kk2];
        }
        __syncthreads();
        #pragma unroll
        for (int kk2 = 0; kk2 < 16; ++kk2) {
            u64 xf[8];
            #pragma unroll
            for (int i = 0; i < 8; i++)
                xf[i] = *(const u64*)&Y2[(ty * 8 + i) * Y_STR + kt + 2 * kk2];
            const double2* wp = (const double2*)(WsD + kk2 * WS_STR + tx * 8);
            double2 wa = wp[0], wb = wp[1], wc = wp[2], wd = wp[3];
            u64 wf[8] = { (u64)__double_as_longlong(wa.x), (u64)__double_as_longlong(wa.y),
                          (u64)__double_as_longlong(wb.x), (u64)__double_as_longlong(wb.y),
                          (u64)__double_as_longlong(wc.x), (u64)__double_as_longlong(wc.y),
                          (u64)__double_as_longlong(wd.x), (u64)__double_as_longlong(wd.y) };
            #pragma unroll
            for (int i = 0; i < 8; i++)
                #pragma unroll
                for (int j = 0; j < 8; j++)
                    acc[i][j] = ffma2(xf[i], wf[j], acc[i][j]);
        }
    }
    // epilogue: eu + bias + residual -> Y1, then per-row LN3 -> outE
    {
        float bb[8];
        #pragma unroll
        for (int j = 0; j < 8; j++) bb[j] = b3[tx * 8 + j];
        #pragma unroll
        for (int i = 0; i < 8; i++) {
            int r = ty * 8 + i;
            int eg = e0 + r;
            #pragma unroll
            for (int j = 0; j < 8; j++) {
                int c = tx * 8 + j;
                float v = unpack_sum(acc[i][j]) + bb[j] + hE[eg * CV + c];
                Y1[r * Y_STR + c] = v;
            }
        }
    }
    __syncthreads();
    {
        int r = tid >> 1, h = tid & 1;
        float s = 0.f, sq = 0.f;
        for (int c = h * 64; c < h * 64 + 64; c++) {
            float v = Y1[r * Y_STR + c];
            s += v; sq += v * v;
        }
        s  += __shfl_xor_sync(0xffffffffu, s, 1);
        sq += __shfl_xor_sync(0xffffffffu, sq, 1);
        float mean = s * (1.0f / CV);
        float var  = sq * (1.0f / CV) - mean * mean;
        float inv  = rsqrtf(var + LN_EPS);
        int eg = e0 + r;
        for (int c = h * 64; c < h * 64 + 64; c++) {
            float v = Y1[r * Y_STR + c];
            outE[eg * CV + c] = (v - mean) * inv * lnw[c] + lnb[c];
        }
    }
}

// ============================================================
// launcher
// ============================================================
extern "C" void kernel_launch(void* const* d_in, const int* in_sizes, int n_in,
                              void* d_out, int out_size)
{
    (void)in_sizes; (void)n_in; (void)out_size;
    const float* hV    = (const float*)d_in[0];
    const float* hE    = (const float*)d_in[1];
    const int*   nbr   = (const int*)  d_in[2];
    const float* mask  = (const float*)d_in[3];
    const float* maskA = (const float*)d_in[4];
    const float* msg_w1 = (const float*)d_in[5];
    const float* msg_b1 = (const float*)d_in[6];
    const float* msg_w2 = (const float*)d_in[7];
    const float* msg_b2 = (const float*)d_in[8];
    const float* msg_w3 = (const float*)d_in[9];
    const float* msg_b3 = (const float*)d_in[10];
    const float* ln1_w  = (const float*)d_in[11];
    const float* ln1_b  = (const float*)d_in[12];
    const float* d_w1   = (const float*)d_in[13];
    const float* d_b1   = (const float*)d_in[14];
    const float* d_w2   = (const float*)d_in[15];
    const float* d_b2   = (const float*)d_in[16];
    const float* ln2_w  = (const float*)d_in[17];
    const float* ln2_b  = (const float*)d_in[18];
    const float* eu_w1  = (const float*)d_in[19];
    const float* eu_b1  = (const float*)d_in[20];
    const float* eu_w2  = (const float*)d_in[21];
    const float* eu_b2  = (const float*)d_in[22];
    const float* eu_w3  = (const float*)d_in[23];
    const float* eu_b3  = (const float*)d_in[24];
    const float* ln3_w  = (const float*)d_in[25];
    const float* ln3_b  = (const float*)d_in[26];

    float* outV = (float*)d_out;
    float* outE = outV + (size_t)N_NODES * CV;

    const int SMEM_MSG = 16 * MSG_XSTR * 8 + 16 * WS_STR * 8 + 2 * 96 * Y_STR * 4;   // 130560
    const int SMEM_D1  = 16 * D_XSTR * 8 + 16 * WS_STR * 8;                          // 25088
    const int SMEM_D2  = 16 * D_XSTR * 8 + 16 * WS_STR * 8 + 64 * Y_STR * 4;         // 58880
    const int SMEM_E   = 16 * E_XSTR * 8 + 16 * WS_STR * 8 + 2 * 128 * Y_STR * 4;    // 168448

    cudaFuncSetAttribute(k_msg,    cudaFuncAttributeMaxDynamicSharedMemorySize, SMEM_MSG);
    cudaFuncSetAttribute(k_dense1, cudaFuncAttributeMaxDynamicSharedMemorySize, SMEM_D1);
    cudaFuncSetAttribute(k_dense2, cudaFuncAttributeMaxDynamicSharedMemorySize, SMEM_D2);
    cudaFuncSetAttribute(k_edge,   cudaFuncAttributeMaxDynamicSharedMemorySize, SMEM_E);

    k_msg<<<N_NODES / 2, 256, SMEM_MSG>>>(hV, hE, nbr, maskA,
                                          msg_w1, msg_b1, msg_w2, msg_b2, msg_w3, msg_b3);
    k_ln1<<<N_NODES, 128>>>(hV, ln1_w, ln1_b);
    k_dense1<<<dim3(N_NODES / 64, 4), 256, SMEM_D1>>>(d_w1, d_b1);
    k_dense2<<<N_NODES / 64, 256, SMEM_D2>>>(d_w2, d_b2, ln2_w, ln2_b, mask, outV);
    k_edge<<<(N_NODES * KNB) / 128, 256, SMEM_E>>>(outV, hE, nbr,
                                                   eu_w1, eu_b1, eu_w2, eu_b2, eu_w3, eu_b3,
                                                   ln3_w, ln3_b, outE);
}

// round 3
// speedup vs baseline: 4.2228x; 4.2228x over previous
#include <cuda_runtime.h>
#include <cuda_bf16.h>
#include <cstdint>

#define N_NODES 16384
#define KNB 48
#define CV 128
#define IN_DIM 384
#define DW 512
#define LN_EPS 1e-5f

#define XS_STR 40    // bf16 units, K-tile stride (32 + 8 pad) -> conflict-free frag loads
#define Y_STR 136    // bf16 units, activation stride
#define Z_STR 132    // float units, LN staging stride

typedef unsigned short u16;

// ---------- scratch (allocation-free) ----------
__device__ u16  g_m[(size_t)N_NODES * KNB * CV];   // per-edge messages, bf16
__device__ float g_v1[N_NODES * CV];               // h_V after LN1
__device__ u16  g_yd[(size_t)N_NODES * DW];        // dense hidden, bf16

// ---------- helpers ----------
__device__ __forceinline__ float gelu_f(float x) {
    return 0.5f * x * (1.0f + erff(x * 0.70710678118654752f));
}

__device__ __forceinline__ void mma16816(float d[4], const unsigned a[4], const unsigned b[2]) {
    asm volatile(
        "mma.sync.aligned.m16n8k16.row.col.f32.bf16.bf16.f32 "
        "{%0,%1,%2,%3}, {%4,%5,%6,%7}, {%8,%9}, {%0,%1,%2,%3};"
        : "+f"(d[0]), "+f"(d[1]), "+f"(d[2]), "+f"(d[3])
        : "r"(a[0]), "r"(a[1]), "r"(a[2]), "r"(a[3]), "r"(b[0]), "r"(b[1]));
}

// One k16 step for a 64x32 warp tile.
// ap0 = &As[(wr0+gr)*sa + kA + ck], bp0 = &Bs[(wc0+gr)*sb + kB + ck]
__device__ __forceinline__ void mma_step(const __nv_bfloat16* ap0, int sa,
                                         const __nv_bfloat16* bp0, int sb,
                                         float acc[4][4][4]) {
    unsigned a[4][4], b[4][2];
    #pragma unroll
    for (int mi = 0; mi < 4; mi++) {
        const __nv_bfloat16* ap = ap0 + mi * 16 * sa;
        a[mi][0] = *(const unsigned*)(ap);
        a[mi][1] = *(const unsigned*)(ap + 8 * sa);
        a[mi][2] = *(const unsigned*)(ap + 8);
        a[mi][3] = *(const unsigned*)(ap + 8 * sa + 8);
    }
    #pragma unroll
    for (int ni = 0; ni < 4; ni++) {
        const __nv_bfloat16* bp = bp0 + ni * 8 * sb;
        b[ni][0] = *(const unsigned*)(bp);
        b[ni][1] = *(const unsigned*)(bp + 8);
    }
    #pragma unroll
    for (int mi = 0; mi < 4; mi++)
        #pragma unroll
        for (int ni = 0; ni < 4; ni++)
            mma16816(acc[mi][ni], a[mi], b[ni]);
}

__device__ __forceinline__ void zero_acc(float acc[4][4][4]) {
    #pragma unroll
    for (int mi = 0; mi < 4; mi++)
        #pragma unroll
        for (int ni = 0; ni < 4; ni++)
            #pragma unroll
            for (int k = 0; k < 4; k++) acc[mi][ni][k] = 0.f;
}

// ============================================================
// Fused 3-layer MLP over 128 concat-gathered edge rows.
//   layer1: IN=384 -> 128 (gelu), layer2: 128->128 (gelu), layer3: 128->128
// mode 0 (message): out = (y + b3) * mask_attend -> g_m (bf16)
// mode 1 (edge):    out = LN3(y + b3 + h_E)      -> outE (fp32)
// ============================================================
__global__ void __launch_bounds__(256, 2)
k_fused(const float* __restrict__ hVsrc, const float* __restrict__ hE,
        const int* __restrict__ nbr,
        const float* __restrict__ w1, const float* __restrict__ b1,
        const float* __restrict__ w2, const float* __restrict__ b2,
        const float* __restrict__ w3, const float* __restrict__ b3,
        const float* __restrict__ maskA,
        const float* __restrict__ lnw, const float* __restrict__ lnb,
        float* __restrict__ outE, int mode)
{
    extern __shared__ char sm[];
    __nv_bfloat16* Xs = (__nv_bfloat16*)sm;      // [128][XS_STR]
    __nv_bfloat16* Ws = Xs + 128 * XS_STR;       // [128][XS_STR]
    __nv_bfloat16* Y1 = Ws + 128 * XS_STR;       // [128][Y_STR]
    __nv_bfloat16* Y2 = Y1 + 128 * Y_STR;        // [128][Y_STR]
    float* Zf = (float*)Y1;                      // [128][Z_STR] overlays Y1+Y2

    const int tid = threadIdx.x;
    const int w = tid >> 5, lane = tid & 31;
    const int wr0 = (w & 1) * 64, wc0 = (w >> 1) * 32;
    const int gr = lane >> 2, ck = (lane & 3) * 2;
    const int e0 = blockIdx.x * 128;

    float acc[4][4][4];
    zero_acc(acc);

    // -------- layer 1: K = 384 (gathered concat input) --------
    for (int kt = 0; kt < IN_DIM; kt += 32) {
        __syncthreads();
        for (int e = tid; e < 128 * 16; e += 256) {
            int r = e >> 4, q = e & 15;
            int eg = e0 + r;
            int c = kt + 2 * q;
            float2 val;
            if (c < CV) {
                val = *(const float2*)&hVsrc[(eg / KNB) * CV + c];
            } else if (c < 2 * CV) {
                val = *(const float2*)&hE[(size_t)eg * CV + (c - CV)];
            } else {
                val = *(const float2*)&hVsrc[nbr[eg] * CV + (c - 2 * CV)];
            }
            *(__nv_bfloat162*)&Xs[r * XS_STR + 2 * q] = __float22bfloat162_rn(val);
        }
        for (int e = tid; e < 128 * 16; e += 256) {
            int n = e >> 4, q = e & 15;
            float2 val = *(const float2*)&w1[n * IN_DIM + kt + 2 * q];
            *(__nv_bfloat162*)&Ws[n * XS_STR + 2 * q] = __float22bfloat162_rn(val);
        }
        __syncthreads();
        #pragma unroll
        for (int ks = 0; ks < 2; ks++)
            mma_step(Xs + (wr0 + gr) * XS_STR + ks * 16 + ck, XS_STR,
                     Ws + (wc0 + gr) * XS_STR + ks * 16 + ck, XS_STR, acc);
    }
    // epilogue 1: bias + gelu -> Y1 (bf16)
    #pragma unroll
    for (int mi = 0; mi < 4; mi++)
        #pragma unroll
        for (int ni = 0; ni < 4; ni++) {
            int r = wr0 + mi * 16 + gr, c = wc0 + ni * 8 + ck;
            float b0v = b1[c], b1v = b1[c + 1];
            *(__nv_bfloat162*)&Y1[r * Y_STR + c] =
                __floats2bfloat162_rn(gelu_f(acc[mi][ni][0] + b0v), gelu_f(acc[mi][ni][1] + b1v));
            *(__nv_bfloat162*)&Y1[(r + 8) * Y_STR + c] =
                __floats2bfloat162_rn(gelu_f(acc[mi][ni][2] + b0v), gelu_f(acc[mi][ni][3] + b1v));
        }

    // -------- layer 2: K = 128 (A from Y1) --------
    zero_acc(acc);
    for (int kt = 0; kt < CV; kt += 32) {
        __syncthreads();
        for (int e = tid; e < 128 * 16; e += 256) {
            int n = e >> 4, q = e & 15;
            float2 val = *(const float2*)&w2[n * CV + kt + 2 * q];
            *(__nv_bfloat162*)&Ws[n * XS_STR + 2 * q] = __float22bfloat162_rn(val);
        }
        __syncthreads();
        #pragma unroll
        for (int ks = 0; ks < 2; ks++)
            mma_step(Y1 + (wr0 + gr) * Y_STR + kt + ks * 16 + ck, Y_STR,
                     Ws + (wc0 + gr) * XS_STR + ks * 16 + ck, XS_STR, acc);
    }
    __syncthreads();
    #pragma unroll
    for (int mi = 0; mi < 4; mi++)
        #pragma unroll
        for (int ni = 0; ni < 4; ni++) {
            int r = wr0 + mi * 16 + gr, c = wc0 + ni * 8 + ck;
            float b0v = b2[c], b1v = b2[c + 1];
            *(__nv_bfloat162*)&Y2[r * Y_STR + c] =
                __floats2bfloat162_rn(gelu_f(acc[mi][ni][0] + b0v), gelu_f(acc[mi][ni][1] + b1v));
            *(__nv_bfloat162*)&Y2[(r + 8) * Y_STR + c] =
                __floats2bfloat162_rn(gelu_f(acc[mi][ni][2] + b0v), gelu_f(acc[mi][ni][3] + b1v));
        }

    // -------- layer 3: K = 128 (A from Y2) --------
    zero_acc(acc);
    for (int kt = 0; kt < CV; kt += 32) {
        __syncthreads();
        for (int e = tid; e < 128 * 16; e += 256) {
            int n = e >> 4, q = e & 15;
            float2 val = *(const float2*)&w3[n * CV + kt + 2 * q];
            *(__nv_bfloat162*)&Ws[n * XS_STR + 2 * q] = __float22bfloat162_rn(val);
        }
        __syncthreads();
        #pragma unroll
        for (int ks = 0; ks < 2; ks++)
            mma_step(Y2 + (wr0 + gr) * Y_STR + kt + ks * 16 + ck, Y_STR,
                     Ws + (wc0 + gr) * XS_STR + ks * 16 + ck, XS_STR, acc);
    }

    if (mode == 0) {
        // message epilogue: (y + b3) * mask_attend -> g_m (bf16)
        #pragma unroll
        for (int mi = 0; mi < 4; mi++)
            #pragma unroll
            for (int ni = 0; ni < 4; ni++) {
                int r = wr0 + mi * 16 + gr, c = wc0 + ni * 8 + ck;
                int eg1 = e0 + r, eg2 = e0 + r + 8;
                float b0v = b3[c], b1v = b3[c + 1];
                float ma1 = maskA[eg1], ma2 = maskA[eg2];
                *(__nv_bfloat162*)&g_m[(size_t)eg1 * CV + c] =
                    __floats2bfloat162_rn((acc[mi][ni][0] + b0v) * ma1, (acc[mi][ni][1] + b1v) * ma1);
                *(__nv_bfloat162*)&g_m[(size_t)eg2 * CV + c] =
                    __floats2bfloat162_rn((acc[mi][ni][2] + b0v) * ma2, (acc[mi][ni][3] + b1v) * ma2);
            }
    } else {
        // edge epilogue: residual + LN3 -> outE
        __syncthreads();  // Y2 reads done before Zf overwrite
        #pragma unroll
        for (int mi = 0; mi < 4; mi++)
            #pragma unroll
            for (int ni = 0; ni < 4; ni++) {
                int r = wr0 + mi * 16 + gr, c = wc0 + ni * 8 + ck;
                float b0v = b3[c], b1v = b3[c + 1];
                float2 res1 = *(const float2*)&hE[(size_t)(e0 + r) * CV + c];
                float2 res2 = *(const float2*)&hE[(size_t)(e0 + r + 8) * CV + c];
                float2 z1 = { acc[mi][ni][0] + b0v + res1.x, acc[mi][ni][1] + b1v + res1.y };
                float2 z2 = { acc[mi][ni][2] + b0v + res2.x, acc[mi][ni][3] + b1v + res2.y };
                *(float2*)&Zf[r * Z_STR + c] = z1;
                *(float2*)&Zf[(r + 8) * Z_STR + c] = z2;
            }
        __syncthreads();
        {
            int r = tid >> 1, h = tid & 1;
            float s = 0.f, sq = 0.f;
            #pragma unroll 8
            for (int c = h * 64; c < h * 64 + 64; c++) {
                float v = Zf[r * Z_STR + c];
                s += v; sq += v * v;
            }
            s  += __shfl_xor_sync(0xffffffffu, s, 1);
            sq += __shfl_xor_sync(0xffffffffu, sq, 1);
            float mean = s * (1.0f / CV);
            float var  = sq * (1.0f / CV) - mean * mean;
            float inv  = rsqrtf(var + LN_EPS);
            size_t eg = (size_t)(e0 + r) * CV;
            for (int c = h * 64; c < h * 64 + 64; c++) {
                float v = Zf[r * Z_STR + c];
                outE[eg + c] = (v - mean) * inv * lnw[c] + lnb[c];
            }
        }
    }
}

// ============================================================
// Reduce messages over K, + residual + LN1 -> g_v1
// ============================================================
__global__ void k_red(const float* __restrict__ hV,
                      const float* __restrict__ w, const float* __restrict__ b)
{
    int n = blockIdx.x, t = threadIdx.x;
    const u16* mp = g_m + (size_t)n * KNB * CV + t;
    float s0 = 0.f;
    #pragma unroll
    for (int k = 0; k < KNB; k++)
        s0 += __bfloat162float(*(const __nv_bfloat16*)&mp[k * CV]);
    float x = hV[n * CV + t] + s0 * (1.0f / 30.0f);
    float s = x, sq = x * x;
    #pragma unroll
    for (int o = 16; o > 0; o >>= 1) {
        s  += __shfl_xor_sync(0xffffffffu, s, o);
        sq += __shfl_xor_sync(0xffffffffu, sq, o);
    }
    __shared__ float ss[4], ssq[4];
    int wid = t >> 5, lane = t & 31;
    if (lane == 0) { ss[wid] = s; ssq[wid] = sq; }
    __syncthreads();
    s  = ss[0] + ss[1] + ss[2] + ss[3];
    sq = ssq[0] + ssq[1] + ssq[2] + ssq[3];
    float mean = s * (1.0f / CV);
    float var  = sq * (1.0f / CV) - mean * mean;
    float inv  = rsqrtf(var + LN_EPS);
    g_v1[n * CV + t] = (x - mean) * inv * w[t] + b[t];
}

// ============================================================
// dense1: g_yd = gelu(v1 @ d_w1^T + b1)   [16384, 512] bf16
// block 128x128, grid (128, 4)
// ============================================================
__global__ void __launch_bounds__(256, 2)
k_dense1(const float* __restrict__ w, const float* __restrict__ b)
{
    __shared__ __nv_bfloat16 Xs[128 * XS_STR];
    __shared__ __nv_bfloat16 Ws[128 * XS_STR];
    const int tid = threadIdx.x;
    const int wp = tid >> 5, lane = tid & 31;
    const int wr0 = (wp & 1) * 64, wc0 = (wp >> 1) * 32;
    const int gr = lane >> 2, ck = (lane & 3) * 2;
    const int r0 = blockIdx.x * 128, c0 = blockIdx.y * 128;

    float acc[4][4][4];
    zero_acc(acc);
    for (int kt = 0; kt < CV; kt += 32) {
        __syncthreads();
        for (int e = tid; e < 128 * 16; e += 256) {
            int r = e >> 4, q = e & 15;
            float2 val = *(const float2*)&g_v1[(r0 + r) * CV + kt + 2 * q];
            *(__nv_bfloat162*)&Xs[r * XS_STR + 2 * q] = __float22bfloat162_rn(val);
        }
        for (int e = tid; e < 128 * 16; e += 256) {
            int n = e >> 4, q = e & 15;
            float2 val = *(const float2*)&w[(c0 + n) * CV + kt + 2 * q];
            *(__nv_bfloat162*)&Ws[n * XS_STR + 2 * q] = __float22bfloat162_rn(val);
        }
        __syncthreads();
        #pragma unroll
        for (int ks = 0; ks < 2; ks++)
            mma_step(Xs + (wr0 + gr) * XS_STR + ks * 16 + ck, XS_STR,
                     Ws + (wc0 + gr) * XS_STR + ks * 16 + ck, XS_STR, acc);
    }
    #pragma unroll
    for (int mi = 0; mi < 4; mi++)
        #pragma unroll
        for (int ni = 0; ni < 4; ni++) {
            int r = wr0 + mi * 16 + gr, c = wc0 + ni * 8 + ck;
            int cg = c0 + c;
            float b0v = b[cg], b1v = b[cg + 1];
            *(__nv_bfloat162*)&g_yd[(size_t)(r0 + r) * DW + cg] =
                __floats2bfloat162_rn(gelu_f(acc[mi][ni][0] + b0v), gelu_f(acc[mi][ni][1] + b1v));
            *(__nv_bfloat162*)&g_yd[(size_t)(r0 + r + 8) * DW + cg] =
                __floats2bfloat162_rn(gelu_f(acc[mi][ni][2] + b0v), gelu_f(acc[mi][ni][3] + b1v));
        }
}

// ============================================================
// dense2: z = g_yd @ d_w2^T + b2 + v1; outV = LN2(z) * mask
// block 128 rows x 128 cols, K = 512
// ============================================================
__global__ void __launch_bounds__(256, 2)
k_dense2(const float* __restrict__ w, const float* __restrict__ b,
         const float* __restrict__ lnw, const float* __restrict__ lnb,
         const float* __restrict__ mask, float* __restrict__ outV)
{
    extern __shared__ char sm[];
    __nv_bfloat16* Xs = (__nv_bfloat16*)sm;      // [128][XS_STR]
    __nv_bfloat16* Ws = Xs + 128 * XS_STR;       // [128][XS_STR]
    float* Zf = (float*)(Ws + 128 * XS_STR);     // [128][Z_STR]

    const int tid = threadIdx.x;
    const int wp = tid >> 5, lane = tid & 31;
    const int wr0 = (wp & 1) * 64, wc0 = (wp >> 1) * 32;
    const int gr = lane >> 2, ck = (lane & 3) * 2;
    const int r0 = blockIdx.x * 128;

    float acc[4][4][4];
    zero_acc(acc);
    for (int kt = 0; kt < DW; kt += 32) {
        __syncthreads();
        for (int e = tid; e < 128 * 16; e += 256) {
            int r = e >> 4, q = e & 15;
            *(unsigned*)&Xs[r * XS_STR + 2 * q] =
                *(const unsigned*)&g_yd[(size_t)(r0 + r) * DW + kt + 2 * q];
        }
        for (int e = tid; e < 128 * 16; e += 256) {
            int n = e >> 4, q = e & 15;
            float2 val = *(const float2*)&w[n * DW + kt + 2 * q];
            *(__nv_bfloat162*)&Ws[n * XS_STR + 2 * q] = __float22bfloat162_rn(val);
        }
        __syncthreads();
        #pragma unroll
        for (int ks = 0; ks < 2; ks++)
            mma_step(Xs + (wr0 + gr) * XS_STR + ks * 16 + ck, XS_STR,
                     Ws + (wc0 + gr) * XS_STR + ks * 16 + ck, XS_STR, acc);
    }
    __syncthreads();
    #pragma unroll
    for (int mi = 0; mi < 4; mi++)
        #pragma unroll
        for (int ni = 0; ni < 4; ni++) {
            int r = wr0 + mi * 16 + gr, c = wc0 + ni * 8 + ck;
            float b0v = b[c], b1v = b[c + 1];
            float2 res1 = *(const float2*)&g_v1[(r0 + r) * CV + c];
            float2 res2 = *(const float2*)&g_v1[(r0 + r + 8) * CV + c];
            float2 z1 = { acc[mi][ni][0] + b0v + res1.x, acc[mi][ni][1] + b1v + res1.y };
            float2 z2 = { acc[mi][ni][2] + b0v + res2.x, acc[mi][ni][3] + b1v + res2.y };
            *(float2*)&Zf[r * Z_STR + c] = z1;
            *(float2*)&Zf[(r + 8) * Z_STR + c] = z2;
        }
    __syncthreads();
    {
        int r = tid >> 1, h = tid & 1;
        float s = 0.f, sq = 0.f;
        #pragma unroll 8
        for (int c = h * 64; c < h * 64 + 64; c++) {
            float v = Zf[r * Z_STR + c];
            s += v; sq += v * v;
        }
        s  += __shfl_xor_sync(0xffffffffu, s, 1);
        sq += __shfl_xor_sync(0xffffffffu, sq, 1);
        float mean = s * (1.0f / CV);
        float var  = sq * (1.0f / CV) - mean * mean;
        float inv  = rsqrtf(var + LN_EPS);
        float mk = mask[r0 + r];
        for (int c = h * 64; c < h * 64 + 64; c++) {
            float v = Zf[r * Z_STR + c];
            outV[(r0 + r) * CV + c] = ((v - mean) * inv * lnw[c] + lnb[c]) * mk;
        }
    }
}

// ============================================================
// launcher
// ============================================================
extern "C" void kernel_launch(void* const* d_in, const int* in_sizes, int n_in,
                              void* d_out, int out_size)
{
    (void)in_sizes; (void)n_in; (void)out_size;
    const float* hV    = (const float*)d_in[0];
    const float* hE    = (const float*)d_in[1];
    const int*   nbr   = (const int*)  d_in[2];
    const float* mask  = (const float*)d_in[3];
    const float* maskA = (const float*)d_in[4];
    const float* msg_w1 = (const float*)d_in[5];
    const float* msg_b1 = (const float*)d_in[6];
    const float* msg_w2 = (const float*)d_in[7];
    const float* msg_b2 = (const float*)d_in[8];
    const float* msg_w3 = (const float*)d_in[9];
    const float* msg_b3 = (const float*)d_in[10];
    const float* ln1_w  = (const float*)d_in[11];
    const float* ln1_b  = (const float*)d_in[12];
    const float* d_w1   = (const float*)d_in[13];
    const float* d_b1   = (const float*)d_in[14];
    const float* d_w2   = (const float*)d_in[15];
    const float* d_b2   = (const float*)d_in[16];
    const float* ln2_w  = (const float*)d_in[17];
    const float* ln2_b  = (const float*)d_in[18];
    const float* eu_w1  = (const float*)d_in[19];
    const float* eu_b1  = (const float*)d_in[20];
    const float* eu_w2  = (const float*)d_in[21];
    const float* eu_b2  = (const float*)d_in[22];
    const float* eu_w3  = (const float*)d_in[23];
    const float* eu_b3  = (const float*)d_in[24];
    const float* ln3_w  = (const float*)d_in[25];
    const float* ln3_b  = (const float*)d_in[26];

    float* outV = (float*)d_out;
    float* outE = outV + (size_t)N_NODES * CV;

    const int SMEM_F  = (128 * XS_STR * 2 + 128 * Y_STR * 2) * 2;       // 90112
    const int SMEM_D2 = 128 * XS_STR * 2 * 2 + 128 * Z_STR * 4;         // 88064

    cudaFuncSetAttribute(k_fused,  cudaFuncAttributeMaxDynamicSharedMemorySize, SMEM_F);
    cudaFuncSetAttribute(k_dense2, cudaFuncAttributeMaxDynamicSharedMemorySize, SMEM_D2);

    const int EGRID = (N_NODES * KNB) / 128;  // 6144

    // message phase
    k_fused<<<EGRID, 256, SMEM_F>>>(hV, hE, nbr,
                                    msg_w1, msg_b1, msg_w2, msg_b2, msg_w3, msg_b3,
                                    maskA, ln3_w, ln3_b, outE, 0);
    // reduce + LN1
    k_red<<<N_NODES, 128>>>(hV, ln1_w, ln1_b);
    // dense
    k_dense1<<<dim3(N_NODES / 128, 4), 256>>>(d_w1, d_b1);
    k_dense2<<<N_NODES / 128, 256, SMEM_D2>>>(d_w2, d_b2, ln2_w, ln2_b, mask, outV);
    // edge update phase (reads refreshed h_V from d_out)
    k_fused<<<EGRID, 256, SMEM_F>>>(outV, hE, nbr,
                                    eu_w1, eu_b1, eu_w2, eu_b2, eu_w3, eu_b3,
                                    maskA, ln3_w, ln3_b, outE, 1);
}

// round 4
// speedup vs baseline: 7.7378x; 1.8324x over previous
#include <cuda_runtime.h>
#include <cuda_bf16.h>
#include <cstdint>

#define N_NODES 16384
#define KNB 48
#define EDGES (N_NODES * KNB)
#define CV 128
#define IN_DIM 384
#define DW 512
#define LN_EPS 1e-5f

#define STR 136      // bf16 units, tile stride (128 + 8 pad)
#define Z_STR 132    // float units, LN staging stride

typedef unsigned short u16;

// ---------- scratch (allocation-free) ----------
__device__ u16  g_he[(size_t)EDGES * CV];          // hE in bf16
__device__ u16  g_m[(size_t)EDGES * CV];           // per-edge messages, bf16
__device__ u16  g_aS[N_NODES * CV];                // W_self @ hV + b1 (bf16)
__device__ u16  g_aN[N_NODES * CV];                // W_nbr @ hV (bf16)
__device__ float g_v1[N_NODES * CV];               // h_V after LN1
__device__ u16  g_yd[(size_t)N_NODES * DW];        // dense hidden, bf16
// pre-converted weights (bf16)
__device__ u16 g_w1em[CV * CV], g_w2m[CV * CV], g_w3m[CV * CV];
__device__ u16 g_w1ee[CV * CV], g_w2e[CV * CV], g_w3e[CV * CV];
__device__ u16 g_dw1[DW * CV], g_dw2[CV * DW];

// ---------- helpers ----------
__device__ __forceinline__ float gelu_f(float x) {
    float y = 0.79788456080286536f * x * (1.0f + 0.044715f * x * x);
    float t; asm("tanh.approx.f32 %0, %1;" : "=f"(t) : "f"(y));
    return 0.5f * x * (1.0f + t);
}

__device__ __forceinline__ void mma16816(float d[4], const unsigned a[4], const unsigned b[2]) {
    asm volatile(
        "mma.sync.aligned.m16n8k16.row.col.f32.bf16.bf16.f32 "
        "{%0,%1,%2,%3}, {%4,%5,%6,%7}, {%8,%9}, {%0,%1,%2,%3};"
        : "+f"(d[0]), "+f"(d[1]), "+f"(d[2]), "+f"(d[3])
        : "r"(a[0]), "r"(a[1]), "r"(a[2]), "r"(a[3]), "r"(b[0]), "r"(b[1]));
}

// One k16 step for a 64x32 warp tile.
__device__ __forceinline__ void mma_step(const u16* ap0, int sa,
                                         const u16* bp0, int sb,
                                         float acc[4][4][4]) {
    unsigned a[4][4], b[4][2];
    #pragma unroll
    for (int mi = 0; mi < 4; mi++) {
        const u16* ap = ap0 + mi * 16 * sa;
        a[mi][0] = *(const unsigned*)(ap);
        a[mi][1] = *(const unsigned*)(ap + 8 * sa);
        a[mi][2] = *(const unsigned*)(ap + 8);
        a[mi][3] = *(const unsigned*)(ap + 8 * sa + 8);
    }
    #pragma unroll
    for (int ni = 0; ni < 4; ni++) {
        const u16* bp = bp0 + ni * 8 * sb;
        b[ni][0] = *(const unsigned*)(bp);
        b[ni][1] = *(const unsigned*)(bp + 8);
    }
    #pragma unroll
    for (int mi = 0; mi < 4; mi++)
        #pragma unroll
        for (int ni = 0; ni < 4; ni++)
            mma16816(acc[mi][ni], a[mi], b[ni]);
}

__device__ __forceinline__ void zero_acc(float acc[4][4][4]) {
    #pragma unroll
    for (int mi = 0; mi < 4; mi++)
        #pragma unroll
        for (int ni = 0; ni < 4; ni++)
            #pragma unroll
            for (int k = 0; k < 4; k++) acc[mi][ni][k] = 0.f;
}

__device__ __forceinline__ __nv_bfloat162 bf2(float a, float b) {
    return __floats2bfloat162_rn(a, b);
}

// ============================================================
// prep: fp32 -> bf16 elementwise (float4 granularity)
// ============================================================
__global__ void k_cvt(const float* __restrict__ s, u16* __restrict__ d, int n4)
{
    int i = blockIdx.x * blockDim.x + threadIdx.x;
    if (i < n4) {
        float4 v = ((const float4*)s)[i];
        __nv_bfloat162 a = bf2(v.x, v.y), b = bf2(v.z, v.w);
        uint2 o = { *(unsigned*)&a, *(unsigned*)&b };
        ((uint2*)d)[i] = o;
    }
}

// extract middle 128 cols of a [128 x 384] weight -> bf16 [128 x 128]
__global__ void k_cvt_w1e(const float* __restrict__ w1, u16* __restrict__ dst)
{
    int i = blockIdx.x * 256 + threadIdx.x;
    int o = i >> 7, c = i & 127;
    dst[i] = __bfloat16_as_ushort(__float2bfloat16(w1[o * IN_DIM + CV + c]));
}

// ============================================================
// node precompute: aS = W_self @ hV + b1 (cg=0), aN = W_nbr @ hV (cg=1)
// block 128 rows x 128 cols, K = 128. grid (N/128, 2)
// ============================================================
__global__ void __launch_bounds__(256, 2)
k_nodepre(const float* __restrict__ hVsrc, const float* __restrict__ w1,
          const float* __restrict__ b1)
{
    extern __shared__ char sm[];
    u16* Xs = (u16*)sm;          // [128][STR]
    u16* Ws = Xs + 128 * STR;    // [128][STR]
    const int tid = threadIdx.x;
    const int wp = tid >> 5, lane = tid & 31;
    const int wr0 = (wp & 1) * 64, wc0 = (wp >> 1) * 32;
    const int gr = lane >> 2, ck = (lane & 3) * 2;
    const int r0 = blockIdx.x * 128;
    const int cg = blockIdx.y;
    const int koff = cg ? 2 * CV : 0;
    u16* dst = cg ? g_aN : g_aS;

    for (int e = tid; e < 128 * 32; e += 256) {
        int r = e >> 5, q = e & 31;
        float4 v = *(const float4*)&hVsrc[(r0 + r) * CV + 4 * q];
        __nv_bfloat162 a = bf2(v.x, v.y), b = bf2(v.z, v.w);
        uint2 o = { *(unsigned*)&a, *(unsigned*)&b };
        *(uint2*)&Xs[r * STR + 4 * q] = o;
    }
    for (int e = tid; e < 128 * 32; e += 256) {
        int n = e >> 5, q = e & 31;
        float4 v = *(const float4*)&w1[n * IN_DIM + koff + 4 * q];
        __nv_bfloat162 a = bf2(v.x, v.y), b = bf2(v.z, v.w);
        uint2 o = { *(unsigned*)&a, *(unsigned*)&b };
        *(uint2*)&Ws[n * STR + 4 * q] = o;
    }
    __syncthreads();
    float acc[4][4][4];
    zero_acc(acc);
    #pragma unroll
    for (int ks = 0; ks < 8; ks++)
        mma_step(Xs + (wr0 + gr) * STR + ks * 16 + ck, STR,
                 Ws + (wc0 + gr) * STR + ks * 16 + ck, STR, acc);
    #pragma unroll
    for (int mi = 0; mi < 4; mi++)
        #pragma unroll
        for (int ni = 0; ni < 4; ni++) {
            int r = wr0 + mi * 16 + gr, c = wc0 + ni * 8 + ck;
            float b0v = cg ? 0.f : b1[c], b1v = cg ? 0.f : b1[c + 1];
            *(__nv_bfloat162*)&dst[(r0 + r) * CV + c] = bf2(acc[mi][ni][0] + b0v, acc[mi][ni][1] + b1v);
            *(__nv_bfloat162*)&dst[(r0 + r + 8) * CV + c] = bf2(acc[mi][ni][2] + b0v, acc[mi][ni][3] + b1v);
        }
}

// ============================================================
// Fused 3-layer MLP over 128 edge rows (K=128 per layer, whole-tile staging).
// layer1 acc(hE part) + aS[node] + aN[nbr] -> gelu -> Y1
// mode 0 (message): out = (y3 + b3) * mask_attend -> g_m (bf16)
// mode 1 (edge):    out = LN3(y3 + b3 + h_E)      -> outE (fp32)
// ============================================================
__global__ void __launch_bounds__(256, 2)
k_fused(const float* __restrict__ hEf, const int* __restrict__ nbr,
        const u16* __restrict__ W1e, const u16* __restrict__ W2, const u16* __restrict__ W3,
        const float* __restrict__ b2, const float* __restrict__ b3,
        const float* __restrict__ maskA,
        const float* __restrict__ lnw, const float* __restrict__ lnb,
        float* __restrict__ outE, int mode)
{
    extern __shared__ char sm[];
    u16* Xs = (u16*)sm;          // [128][STR]
    u16* Ws = Xs + 128 * STR;    // [128][STR]
    u16* Y1 = Ws + 128 * STR;    // [128][STR]
    u16* Y2 = Xs;                // overlay (Xs dead after layer 1)
    float* Zf = (float*)Ws;      // overlay Ws+Y1 (mode-1 epilogue)
    __shared__ int nbrS[128];

    const int tid = threadIdx.x;
    const int wp = tid >> 5, lane = tid & 31;
    const int wr0 = (wp & 1) * 64, wc0 = (wp >> 1) * 32;
    const int gr = lane >> 2, ck = (lane & 3) * 2;
    const int e0 = blockIdx.x * 128;

    // stage X (hE bf16) + nbr + W1e
    for (int e = tid; e < 128 * 16; e += 256) {
        int r = e >> 4, q = e & 15;
        ((uint4*)&Xs[r * STR])[q] = ((const uint4*)&g_he[(size_t)(e0 + r) * CV])[q];
    }
    if (tid < 128) nbrS[tid] = nbr[e0 + tid];
    for (int e = tid; e < 128 * 16; e += 256) {
        int n = e >> 4, q = e & 15;
        ((uint4*)&Ws[n * STR])[q] = ((const uint4*)&W1e[n * CV])[q];
    }
    __syncthreads();

    float acc[4][4][4];
    zero_acc(acc);
    #pragma unroll
    for (int ks = 0; ks < 8; ks++)
        mma_step(Xs + (wr0 + gr) * STR + ks * 16 + ck, STR,
                 Ws + (wc0 + gr) * STR + ks * 16 + ck, STR, acc);
    // epi 1a: raw acc -> Y1 (bf16)
    #pragma unroll
    for (int mi = 0; mi < 4; mi++)
        #pragma unroll
        for (int ni = 0; ni < 4; ni++) {
            int r = wr0 + mi * 16 + gr, c = wc0 + ni * 8 + ck;
            *(__nv_bfloat162*)&Y1[r * STR + c] = bf2(acc[mi][ni][0], acc[mi][ni][1]);
            *(__nv_bfloat162*)&Y1[(r + 8) * STR + c] = bf2(acc[mi][ni][2], acc[mi][ni][3]);
        }
    __syncthreads();
    // epi 1b: += aS[node] + aN[nbr], gelu (row-major, coalesced 16B)
    {
        int r = tid >> 1, h = tid & 1;
        int eg = e0 + r;
        int node = eg / KNB;
        int nb = nbrS[r];
        u16* yp = &Y1[r * STR + h * 64];
        const u16* ap = &g_aS[node * CV + h * 64];
        const u16* np = &g_aN[nb * CV + h * 64];
        #pragma unroll
        for (int t4 = 0; t4 < 8; t4++) {
            uint4 yv = *(uint4*)(yp + t4 * 8);
            uint4 av = *(const uint4*)(ap + t4 * 8);
            uint4 nv = *(const uint4*)(np + t4 * 8);
            unsigned* yw = (unsigned*)&yv;
            unsigned* aw = (unsigned*)&av;
            unsigned* nw = (unsigned*)&nv;
            #pragma unroll
            for (int c2 = 0; c2 < 4; c2++) {
                float2 y = __bfloat1622float2(*(__nv_bfloat162*)&yw[c2]);
                float2 a = __bfloat1622float2(*(__nv_bfloat162*)&aw[c2]);
                float2 n = __bfloat1622float2(*(__nv_bfloat162*)&nw[c2]);
                __nv_bfloat162 o = bf2(gelu_f(y.x + a.x + n.x), gelu_f(y.y + a.y + n.y));
                yw[c2] = *(unsigned*)&o;
            }
            *(uint4*)(yp + t4 * 8) = yv;
        }
    }
    // stage W2 (Ws reads from layer-1 mma already complete)
    for (int e = tid; e < 128 * 16; e += 256) {
        int n = e >> 4, q = e & 15;
        ((uint4*)&Ws[n * STR])[q] = ((const uint4*)&W2[n * CV])[q];
    }
    __syncthreads();

    // layer 2
    zero_acc(acc);
    #pragma unroll
    for (int ks = 0; ks < 8; ks++)
        mma_step(Y1 + (wr0 + gr) * STR + ks * 16 + ck, STR,
                 Ws + (wc0 + gr) * STR + ks * 16 + ck, STR, acc);
    #pragma unroll
    for (int mi = 0; mi < 4; mi++)
        #pragma unroll
        for (int ni = 0; ni < 4; ni++) {
            int r = wr0 + mi * 16 + gr, c = wc0 + ni * 8 + ck;
            float b0v = b2[c], b1v = b2[c + 1];
            *(__nv_bfloat162*)&Y2[r * STR + c] =
                bf2(gelu_f(acc[mi][ni][0] + b0v), gelu_f(acc[mi][ni][1] + b1v));
            *(__nv_bfloat162*)&Y2[(r + 8) * STR + c] =
                bf2(gelu_f(acc[mi][ni][2] + b0v), gelu_f(acc[mi][ni][3] + b1v));
        }
    __syncthreads();
    for (int e = tid; e < 128 * 16; e += 256) {
        int n = e >> 4, q = e & 15;
        ((uint4*)&Ws[n * STR])[q] = ((const uint4*)&W3[n * CV])[q];
    }
    __syncthreads();

    // layer 3
    zero_acc(acc);
    #pragma unroll
    for (int ks = 0; ks < 8; ks++)
        mma_step(Y2 + (wr0 + gr) * STR + ks * 16 + ck, STR,
                 Ws + (wc0 + gr) * STR + ks * 16 + ck, STR, acc);

    if (mode == 0) {
        #pragma unroll
        for (int mi = 0; mi < 4; mi++)
            #pragma unroll
            for (int ni = 0; ni < 4; ni++) {
                int r = wr0 + mi * 16 + gr, c = wc0 + ni * 8 + ck;
                int eg1 = e0 + r, eg2 = e0 + r + 8;
                float b0v = b3[c], b1v = b3[c + 1];
                float ma1 = maskA[eg1], ma2 = maskA[eg2];
                *(__nv_bfloat162*)&g_m[(size_t)eg1 * CV + c] =
                    bf2((acc[mi][ni][0] + b0v) * ma1, (acc[mi][ni][1] + b1v) * ma1);
                *(__nv_bfloat162*)&g_m[(size_t)eg2 * CV + c] =
                    bf2((acc[mi][ni][2] + b0v) * ma2, (acc[mi][ni][3] + b1v) * ma2);
            }
    } else {
        __syncthreads();  // all mma reads of Ws/Y1 done before Zf overlay
        #pragma unroll
        for (int mi = 0; mi < 4; mi++)
            #pragma unroll
            for (int ni = 0; ni < 4; ni++) {
                int r = wr0 + mi * 16 + gr, c = wc0 + ni * 8 + ck;
                float b0v = b3[c], b1v = b3[c + 1];
                float2 res1 = *(const float2*)&hEf[(size_t)(e0 + r) * CV + c];
                float2 res2 = *(const float2*)&hEf[(size_t)(e0 + r + 8) * CV + c];
                *(float2*)&Zf[r * Z_STR + c] =
                    make_float2(acc[mi][ni][0] + b0v + res1.x, acc[mi][ni][1] + b1v + res1.y);
                *(float2*)&Zf[(r + 8) * Z_STR + c] =
                    make_float2(acc[mi][ni][2] + b0v + res2.x, acc[mi][ni][3] + b1v + res2.y);
            }
        __syncthreads();
        {
            int r = tid >> 1, h = tid & 1;
            float s = 0.f, sq = 0.f;
            #pragma unroll 8
            for (int c = h * 64; c < h * 64 + 64; c++) {
                float v = Zf[r * Z_STR + c];
                s += v; sq += v * v;
            }
            s  += __shfl_xor_sync(0xffffffffu, s, 1);
            sq += __shfl_xor_sync(0xffffffffu, sq, 1);
            float mean = s * (1.0f / CV);
            float var  = sq * (1.0f / CV) - mean * mean;
            float inv  = rsqrtf(var + LN_EPS);
            size_t eg = (size_t)(e0 + r) * CV;
            for (int c = h * 64; c < h * 64 + 64; c++) {
                float v = Zf[r * Z_STR + c];
                outE[eg + c] = (v - mean) * inv * lnw[c] + lnb[c];
            }
        }
    }
}

// ============================================================
// reduce messages over K, + residual + LN1 -> g_v1
// ============================================================
__global__ void k_red(const float* __restrict__ hV,
                      const float* __restrict__ w, const float* __restrict__ b)
{
    int n = blockIdx.x, t = threadIdx.x;
    const u16* mp = g_m + (size_t)n * KNB * CV + t;
    float s0 = 0.f;
    #pragma unroll
    for (int k = 0; k < KNB; k++)
        s0 += __bfloat162float(*(const __nv_bfloat16*)&mp[k * CV]);
    float x = hV[n * CV + t] + s0 * (1.0f / 30.0f);
    float s = x, sq = x * x;
    #pragma unroll
    for (int o = 16; o > 0; o >>= 1) {
        s  += __shfl_xor_sync(0xffffffffu, s, o);
        sq += __shfl_xor_sync(0xffffffffu, sq, o);
    }
    __shared__ float ss[4], ssq[4];
    int wid = t >> 5, lane = t & 31;
    if (lane == 0) { ss[wid] = s; ssq[wid] = sq; }
    __syncthreads();
    s  = ss[0] + ss[1] + ss[2] + ss[3];
    sq = ssq[0] + ssq[1] + ssq[2] + ssq[3];
    float mean = s * (1.0f / CV);
    float var  = sq * (1.0f / CV) - mean * mean;
    float inv  = rsqrtf(var + LN_EPS);
    g_v1[n * CV + t] = (x - mean) * inv * w[t] + b[t];
}

// ============================================================
// dense1: g_yd = gelu(v1 @ d_w1^T + b1)  [16384, 512], K=128 single stage
// ============================================================
__global__ void __launch_bounds__(256, 2)
k_dense1(const float* __restrict__ b)
{
    extern __shared__ char sm[];
    u16* Xs = (u16*)sm;
    u16* Ws = Xs + 128 * STR;
    const int tid = threadIdx.x;
    const int wp = tid >> 5, lane = tid & 31;
    const int wr0 = (wp & 1) * 64, wc0 = (wp >> 1) * 32;
    const int gr = lane >> 2, ck = (lane & 3) * 2;
    const int r0 = blockIdx.x * 128, c0 = blockIdx.y * 128;

    for (int e = tid; e < 128 * 32; e += 256) {
        int r = e >> 5, q = e & 31;
        float4 v = *(const float4*)&g_v1[(r0 + r) * CV + 4 * q];
        __nv_bfloat162 a = bf2(v.x, v.y), bb = bf2(v.z, v.w);
        uint2 o = { *(unsigned*)&a, *(unsigned*)&bb };
        *(uint2*)&Xs[r * STR + 4 * q] = o;
    }
    for (int e = tid; e < 128 * 16; e += 256) {
        int n = e >> 4, q = e & 15;
        ((uint4*)&Ws[n * STR])[q] = ((const uint4*)&g_dw1[(c0 + n) * CV])[q];
    }
    __syncthreads();
    float acc[4][4][4];
    zero_acc(acc);
    #pragma unroll
    for (int ks = 0; ks < 8; ks++)
        mma_step(Xs + (wr0 + gr) * STR + ks * 16 + ck, STR,
                 Ws + (wc0 + gr) * STR + ks * 16 + ck, STR, acc);
    #pragma unroll
    for (int mi = 0; mi < 4; mi++)
        #pragma unroll
        for (int ni = 0; ni < 4; ni++) {
            int r = wr0 + mi * 16 + gr, cg = c0 + wc0 + ni * 8 + ck;
            float b0v = b[cg], b1v = b[cg + 1];
            *(__nv_bfloat162*)&g_yd[(size_t)(r0 + r) * DW + cg] =
                bf2(gelu_f(acc[mi][ni][0] + b0v), gelu_f(acc[mi][ni][1] + b1v));
            *(__nv_bfloat162*)&g_yd[(size_t)(r0 + r + 8) * DW + cg] =
                bf2(gelu_f(acc[mi][ni][2] + b0v), gelu_f(acc[mi][ni][3] + b1v));
        }
}

// ============================================================
// dense2: z = g_yd @ d_w2^T + b2 + v1; outV = LN2(z) * mask. K=512 in 4 chunks
// ============================================================
__global__ void __launch_bounds__(256, 2)
k_dense2(const float* __restrict__ b,
         const float* __restrict__ lnw, const float* __restrict__ lnb,
         const float* __restrict__ mask, float* __restrict__ outV)
{
    extern __shared__ char sm[];
    u16* Xs = (u16*)sm;
    u16* Ws = Xs + 128 * STR;
    float* Zf = (float*)sm;      // overlay after GEMM
    const int tid = threadIdx.x;
    const int wp = tid >> 5, lane = tid & 31;
    const int wr0 = (wp & 1) * 64, wc0 = (wp >> 1) * 32;
    const int gr = lane >> 2, ck = (lane & 3) * 2;
    const int r0 = blockIdx.x * 128;

    float acc[4][4][4];
    zero_acc(acc);
    for (int kt = 0; kt < DW; kt += 128) {
        __syncthreads();
        for (int e = tid; e < 128 * 16; e += 256) {
            int r = e >> 4, q = e & 15;
            ((uint4*)&Xs[r * STR])[q] = ((const uint4*)&g_yd[(size_t)(r0 + r) * DW + kt])[q];
        }
        for (int e = tid; e < 128 * 16; e += 256) {
            int n = e >> 4, q = e & 15;
            ((uint4*)&Ws[n * STR])[q] = ((const uint4*)&g_dw2[n * DW + kt])[q];
        }
        __syncthreads();
        #pragma unroll
        for (int ks = 0; ks < 8; ks++)
            mma_step(Xs + (wr0 + gr) * STR + ks * 16 + ck, STR,
                     Ws + (wc0 + gr) * STR + ks * 16 + ck, STR, acc);
    }
    __syncthreads();
    #pragma unroll
    for (int mi = 0; mi < 4; mi++)
        #pragma unroll
        for (int ni = 0; ni < 4; ni++) {
            int r = wr0 + mi * 16 + gr, c = wc0 + ni * 8 + ck;
            float b0v = b[c], b1v = b[c + 1];
            float2 res1 = *(const float2*)&g_v1[(r0 + r) * CV + c];
            float2 res2 = *(const float2*)&g_v1[(r0 + r + 8) * CV + c];
            *(float2*)&Zf[r * Z_STR + c] =
                make_float2(acc[mi][ni][0] + b0v + res1.x, acc[mi][ni][1] + b1v + res1.y);
            *(float2*)&Zf[(r + 8) * Z_STR + c] =
                make_float2(acc[mi][ni][2] + b0v + res2.x, acc[mi][ni][3] + b1v + res2.y);
        }
    __syncthreads();
    {
        int r = tid >> 1, h = tid & 1;
        float s = 0.f, sq = 0.f;
        #pragma unroll 8
        for (int c = h * 64; c < h * 64 + 64; c++) {
            float v = Zf[r * Z_STR + c];
            s += v; sq += v * v;
        }
        s  += __shfl_xor_sync(0xffffffffu, s, 1);
        sq += __shfl_xor_sync(0xffffffffu, sq, 1);
        float mean = s * (1.0f / CV);
        float var  = sq * (1.0f / CV) - mean * mean;
        float inv  = rsqrtf(var + LN_EPS);
        float mk = mask[r0 + r];
        for (int c = h * 64; c < h * 64 + 64; c++) {
            float v = Zf[r * Z_STR + c];
            outV[(r0 + r) * CV + c] = ((v - mean) * inv * lnw[c] + lnb[c]) * mk;
        }
    }
}

// ============================================================
// launcher
// ============================================================
extern "C" void kernel_launch(void* const* d_in, const int* in_sizes, int n_in,
                              void* d_out, int out_size)
{
    (void)in_sizes; (void)n_in; (void)out_size;
    const float* hV    = (const float*)d_in[0];
    const float* hE    = (const float*)d_in[1];
    const int*   nbr   = (const int*)  d_in[2];
    const float* mask  = (const float*)d_in[3];
    const float* maskA = (const float*)d_in[4];
    const float* msg_w1 = (const float*)d_in[5];
    const float* msg_b1 = (const float*)d_in[6];
    const float* msg_w2 = (const float*)d_in[7];
    const float* msg_b2 = (const float*)d_in[8];
    const float* msg_w3 = (const float*)d_in[9];
    const float* msg_b3 = (const float*)d_in[10];
    const float* ln1_w  = (const float*)d_in[11];
    const float* ln1_b  = (const float*)d_in[12];
    const float* d_w1   = (const float*)d_in[13];
    const float* d_b1   = (const float*)d_in[14];
    const float* d_w2   = (const float*)d_in[15];
    const float* d_b2   = (const float*)d_in[16];
    const float* ln2_w  = (const float*)d_in[17];
    const float* ln2_b  = (const float*)d_in[18];
    const float* eu_w1  = (const float*)d_in[19];
    const float* eu_b1  = (const float*)d_in[20];
    const float* eu_w2  = (const float*)d_in[21];
    const float* eu_b2  = (const float*)d_in[22];
    const float* eu_w3  = (const float*)d_in[23];
    const float* eu_b3  = (const float*)d_in[24];
    const float* ln3_w  = (const float*)d_in[25];
    const float* ln3_b  = (const float*)d_in[26];

    float* outV = (float*)d_out;
    float* outE = outV + (size_t)N_NODES * CV;

    u16 *p_he, *p_w2m, *p_w3m, *p_w2e, *p_w3e, *p_dw1, *p_dw2, *p_w1em, *p_w1ee;
    cudaGetSymbolAddress((void**)&p_he,  g_he);
    cudaGetSymbolAddress((void**)&p_w2m, g_w2m);
    cudaGetSymbolAddress((void**)&p_w3m, g_w3m);
    cudaGetSymbolAddress((void**)&p_w2e, g_w2e);
    cudaGetSymbolAddress((void**)&p_w3e, g_w3e);
    cudaGetSymbolAddress((void**)&p_dw1, g_dw1);
    cudaGetSymbolAddress((void**)&p_dw2, g_dw2);
    cudaGetSymbolAddress((void**)&p_w1em, g_w1em);
    cudaGetSymbolAddress((void**)&p_w1ee, g_w1ee);

    const int SMEM_F  = 3 * 128 * STR * 2;   // 104448
    const int SMEM_G  = 2 * 128 * STR * 2;   // 69632
    cudaFuncSetAttribute(k_fused,   cudaFuncAttributeMaxDynamicSharedMemorySize, SMEM_F);
    cudaFuncSetAttribute(k_nodepre, cudaFuncAttributeMaxDynamicSharedMemorySize, SMEM_G);
    cudaFuncSetAttribute(k_dense1,  cudaFuncAttributeMaxDynamicSharedMemorySize, SMEM_G);
    cudaFuncSetAttribute(k_dense2,  cudaFuncAttributeMaxDynamicSharedMemorySize, SMEM_G);

    // prep: conversions
    {
        int n4 = (EDGES * CV) / 4;
        k_cvt<<<(n4 + 255) / 256, 256>>>(hE, p_he, n4);
        k_cvt<<<16, 256>>>(msg_w2, p_w2m, 4096);
        k_cvt<<<16, 256>>>(msg_w3, p_w3m, 4096);
        k_cvt<<<16, 256>>>(eu_w2, p_w2e, 4096);
        k_cvt<<<16, 256>>>(eu_w3, p_w3e, 4096);
        k_cvt<<<64, 256>>>(d_w1, p_dw1, 16384);
        k_cvt<<<64, 256>>>(d_w2, p_dw2, 16384);
        k_cvt_w1e<<<64, 256>>>(msg_w1, p_w1em);
        k_cvt_w1e<<<64, 256>>>(eu_w1, p_w1ee);
    }

    const int EGRID = EDGES / 128;  // 6144

    // message phase
    k_nodepre<<<dim3(N_NODES / 128, 2), 256, SMEM_G>>>(hV, msg_w1, msg_b1);
    k_fused<<<EGRID, 256, SMEM_F>>>(hE, nbr, p_w1em, p_w2m, p_w3m,
                                    msg_b2, msg_b3, maskA, ln3_w, ln3_b, outE, 0);
    k_red<<<N_NODES, 128>>>(hV, ln1_w, ln1_b);
    // dense phase
    k_dense1<<<dim3(N_NODES / 128, 4), 256, SMEM_G>>>(d_b1);
    k_dense2<<<N_NODES / 128, 256, SMEM_G>>>(d_b2, ln2_w, ln2_b, mask, outV);
    // edge update phase (node precompute on refreshed h_V)
    k_nodepre<<<dim3(N_NODES / 128, 2), 256, SMEM_G>>>(outV, eu_w1, eu_b1);
    k_fused<<<EGRID, 256, SMEM_F>>>(hE, nbr, p_w1ee, p_w2e, p_w3e,
                                    eu_b2, eu_b3, maskA, ln3_w, ln3_b, outE, 1);
}

// round 7
// speedup vs baseline: 8.2391x; 1.0648x over previous
#include <cuda_runtime.h>
#include <cuda_bf16.h>
#include <cstdint>

#define N_NODES 16384
#define KNB 48
#define EDGES (N_NODES * KNB)
#define CV 128
#define IN_DIM 384
#define DW 512
#define LN_EPS 1e-5f

#define STR 136      // bf16 units, tile stride (128 + 8 pad); 272B row stride -> LDSM conflict-free
#define Z_STR 132    // float units, LN staging stride

typedef unsigned short u16;

// ---------- scratch (allocation-free) ----------
__device__ u16  g_m[(size_t)EDGES * CV];           // per-edge messages, bf16
__device__ u16  g_aS[N_NODES * CV];                // W_self @ hV + b1 (bf16)
__device__ u16  g_aN[N_NODES * CV];                // W_nbr @ hV (bf16)
__device__ float g_v1[N_NODES * CV];               // h_V after LN1
__device__ u16  g_yd[(size_t)N_NODES * DW];        // dense hidden, bf16
__device__ u16 g_w1em[CV * CV], g_w2m[CV * CV], g_w3m[CV * CV];
__device__ u16 g_w1ee[CV * CV], g_w2e[CV * CV], g_w3e[CV * CV];
__device__ u16 g_dw1[DW * CV], g_dw2[CV * DW];

// ---------- helpers ----------
__device__ __forceinline__ float gelu_f(float x) {
    float y = 0.79788456080286536f * x * (1.0f + 0.044715f * x * x);
    float t; asm("tanh.approx.f32 %0, %1;" : "=f"(t) : "f"(y));
    return 0.5f * x * (1.0f + t);
}
__device__ __forceinline__ __nv_bfloat162 bf2(float a, float b) {
    return __floats2bfloat162_rn(a, b);
}
__device__ __forceinline__ uint32_t smem_u32(const void* p) {
    uint32_t a;
    asm("{ .reg .u64 t; cvta.to.shared.u64 t, %1; cvt.u32.u64 %0, t; }" : "=r"(a) : "l"(p));
    return a;
}

__device__ __forceinline__ void mma16816(float d[4], const unsigned a[4], const unsigned b[2]) {
    asm volatile(
        "mma.sync.aligned.m16n8k16.row.col.f32.bf16.bf16.f32 "
        "{%0,%1,%2,%3}, {%4,%5,%6,%7}, {%8,%9}, {%0,%1,%2,%3};"
        : "+f"(d[0]), "+f"(d[1]), "+f"(d[2]), "+f"(d[3])
        : "r"(a[0]), "r"(a[1]), "r"(a[2]), "r"(a[3]), "r"(b[0]), "r"(b[1]));
}
__device__ __forceinline__ void ldsm4(unsigned& r0, unsigned& r1, unsigned& r2, unsigned& r3,
                                      uint32_t addr) {
    asm volatile("ldmatrix.sync.aligned.m8n8.x4.shared.b16 {%0,%1,%2,%3}, [%4];"
                 : "=r"(r0), "=r"(r1), "=r"(r2), "=r"(r3) : "r"(addr));
}

// One k16 step for a 64x32 warp tile, LDSM fragment loads.
// aAddr/bAddr: smem byte addresses already including lane offsets
//   base + ((tile0 + (lane&15))*STR + kcol + ((lane>>4)<<3)) * 2
__device__ __forceinline__ void mma_step(uint32_t aAddr, uint32_t bAddr, float acc[4][4][4]) {
    unsigned a[4][4], b[4][2];
    #pragma unroll
    for (int mi = 0; mi < 4; mi++)
        ldsm4(a[mi][0], a[mi][1], a[mi][2], a[mi][3], aAddr + mi * (16 * STR * 2));
    #pragma unroll
    for (int np = 0; np < 2; np++) {
        unsigned r0, r1, r2, r3;
        ldsm4(r0, r1, r2, r3, bAddr + np * (16 * STR * 2));
        b[2 * np][0] = r0;     b[2 * np][1] = r2;
        b[2 * np + 1][0] = r1; b[2 * np + 1][1] = r3;
    }
    #pragma unroll
    for (int mi = 0; mi < 4; mi++)
        #pragma unroll
        for (int ni = 0; ni < 4; ni++)
            mma16816(acc[mi][ni], a[mi], b[ni]);
}

__device__ __forceinline__ void zero_acc(float acc[4][4][4]) {
    #pragma unroll
    for (int mi = 0; mi < 4; mi++)
        #pragma unroll
        for (int ni = 0; ni < 4; ni++)
            #pragma unroll
            for (int k = 0; k < 4; k++) acc[mi][ni][k] = 0.f;
}

// per-thread LDSM lane offset (bytes) within a tile: rows (lane&15), k-half (lane>>4)*8
__device__ __forceinline__ uint32_t ldsm_lane_off(int lane, int tile0) {
    return (uint32_t)(((tile0 + (lane & 15)) * STR + ((lane >> 4) << 3)) * 2);
}

// ============================================================
// prep conversions
// ============================================================
__global__ void k_cvt(const float* __restrict__ s, u16* __restrict__ d, int n4)
{
    int i = blockIdx.x * blockDim.x + threadIdx.x;
    if (i < n4) {
        float4 v = ((const float4*)s)[i];
        __nv_bfloat162 a = bf2(v.x, v.y), b = bf2(v.z, v.w);
        uint2 o = { *(unsigned*)&a, *(unsigned*)&b };
        ((uint2*)d)[i] = o;
    }
}
__global__ void k_cvt_w1e(const float* __restrict__ w1, u16* __restrict__ dst)
{
    int i = blockIdx.x * 256 + threadIdx.x;
    int o = i >> 7, c = i & 127;
    dst[i] = __bfloat16_as_ushort(__float2bfloat16(w1[o * IN_DIM + CV + c]));
}

// ============================================================
// node precompute: aS = W_self @ hV + b1 (cg=0), aN = W_nbr @ hV (cg=1)
// ============================================================
__global__ void __launch_bounds__(256, 2)
k_nodepre(const float* __restrict__ hVsrc, const float* __restrict__ w1,
          const float* __restrict__ b1)
{
    extern __shared__ char smx[];
    u16* Xs = (u16*)smx;
    u16* Ws = Xs + 128 * STR;
    const int tid = threadIdx.x;
    const int wp = tid >> 5, lane = tid & 31;
    const int wr0 = (wp & 1) * 64, wc0 = (wp >> 1) * 32;
    const int gr = lane >> 2, ck = (lane & 3) * 2;
    const int r0 = blockIdx.x * 128;
    const int cg = blockIdx.y;
    const int koff = cg ? 2 * CV : 0;
    u16* dst = cg ? g_aN : g_aS;

    for (int e = tid; e < 128 * 32; e += 256) {
        int r = e >> 5, q = e & 31;
        float4 v = *(const float4*)&hVsrc[(r0 + r) * CV + 4 * q];
        __nv_bfloat162 a = bf2(v.x, v.y), b = bf2(v.z, v.w);
        uint2 o = { *(unsigned*)&a, *(unsigned*)&b };
        *(uint2*)&Xs[r * STR + 4 * q] = o;
    }
    for (int e = tid; e < 128 * 32; e += 256) {
        int n = e >> 5, q = e & 31;
        float4 v = *(const float4*)&w1[n * IN_DIM + koff + 4 * q];
        __nv_bfloat162 a = bf2(v.x, v.y), b = bf2(v.z, v.w);
        uint2 o = { *(unsigned*)&a, *(unsigned*)&b };
        *(uint2*)&Ws[n * STR + 4 * q] = o;
    }
    __syncthreads();
    uint32_t aA = smem_u32(Xs) + ldsm_lane_off(lane, wr0);
    uint32_t bA = smem_u32(Ws) + ldsm_lane_off(lane, wc0);
    float acc[4][4][4];
    zero_acc(acc);
    #pragma unroll
    for (int ks = 0; ks < 8; ks++)
        mma_step(aA + ks * 32, bA + ks * 32, acc);
    #pragma unroll
    for (int mi = 0; mi < 4; mi++)
        #pragma unroll
        for (int ni = 0; ni < 4; ni++) {
            int r = wr0 + mi * 16 + gr, c = wc0 + ni * 8 + ck;
            float b0v = cg ? 0.f : b1[c], b1v = cg ? 0.f : b1[c + 1];
            *(__nv_bfloat162*)&dst[(r0 + r) * CV + c] = bf2(acc[mi][ni][0] + b0v, acc[mi][ni][1] + b1v);
            *(__nv_bfloat162*)&dst[(r0 + r + 8) * CV + c] = bf2(acc[mi][ni][2] + b0v, acc[mi][ni][3] + b1v);
        }
}

// ============================================================
// Fused 3-layer MLP over 128 edge rows (K=128 per layer).
// mode 0 (message): out = (y + b3) * mask_attend -> g_m (bf16)
// mode 1 (edge):    out = LN3(y + b3 + h_E)      -> outE (fp32)
// ============================================================
__global__ void __launch_bounds__(256, 2)
k_fused(const float* __restrict__ hEf, const int* __restrict__ nbr,
        const u16* __restrict__ W1e, const u16* __restrict__ W2, const u16* __restrict__ W3,
        const float* __restrict__ b2, const float* __restrict__ b3,
        const float* __restrict__ maskA,
        const float* __restrict__ lnw, const float* __restrict__ lnb,
        float* __restrict__ outE, int mode)
{
    extern __shared__ char sm[];
    u16* Xs = (u16*)sm;          // [128][STR]
    u16* Ws = Xs + 128 * STR;    // [128][STR]
    u16* Y1 = Ws + 128 * STR;    // [128][STR]
    u16* Y2 = Xs;                // overlay (Xs dead after layer 1)
    float* Zf = (float*)Ws;      // overlay Ws+Y1 (mode-1 epilogue)
    __shared__ int nbrS[128];

    const int tid = threadIdx.x;
    const int wp = tid >> 5, lane = tid & 31;
    const int wr0 = (wp & 1) * 64, wc0 = (wp >> 1) * 32;
    const int gr = lane >> 2, ck = (lane & 3) * 2;
    const int e0 = blockIdx.x * 128;

    const uint32_t laneA = ldsm_lane_off(lane, wr0);
    const uint32_t laneB = ldsm_lane_off(lane, wc0);
    const uint32_t XsA = smem_u32(Xs) + laneA;
    const uint32_t WsB = smem_u32(Ws) + laneB;
    const uint32_t Y1A = smem_u32(Y1) + laneA;

    // stage X: hE fp32 -> bf16 in-kernel
    for (int e = tid; e < 128 * 16; e += 256) {
        int r = e >> 4, q = e & 15;
        const float4* src = (const float4*)&hEf[(size_t)(e0 + r) * CV + q * 8];
        float4 v0 = src[0], v1 = src[1];
        __nv_bfloat162 p0 = bf2(v0.x, v0.y), p1 = bf2(v0.z, v0.w);
        __nv_bfloat162 p2 = bf2(v1.x, v1.y), p3 = bf2(v1.z, v1.w);
        uint4 o = { *(unsigned*)&p0, *(unsigned*)&p1, *(unsigned*)&p2, *(unsigned*)&p3 };
        *(uint4*)&Xs[r * STR + q * 8] = o;
    }
    if (tid < 128) nbrS[tid] = nbr[e0 + tid];
    for (int e = tid; e < 128 * 16; e += 256) {
        int n = e >> 4, q = e & 15;
        ((uint4*)&Ws[n * STR])[q] = ((const uint4*)&W1e[n * CV])[q];
    }
    __syncthreads();

    float acc[4][4][4];
    zero_acc(acc);
    #pragma unroll
    for (int ks = 0; ks < 8; ks++)
        mma_step(XsA + ks * 32, WsB + ks * 32, acc);
    // epi 1a: raw acc -> Y1 (bf16)
    #pragma unroll
    for (int mi = 0; mi < 4; mi++)
        #pragma unroll
        for (int ni = 0; ni < 4; ni++) {
            int r = wr0 + mi * 16 + gr, c = wc0 + ni * 8 + ck;
            *(__nv_bfloat162*)&Y1[r * STR + c] = bf2(acc[mi][ni][0], acc[mi][ni][1]);
            *(__nv_bfloat162*)&Y1[(r + 8) * STR + c] = bf2(acc[mi][ni][2], acc[mi][ni][3]);
        }
    __syncthreads();
    // epi 1b: += aS[node] + aN[nbr], gelu (row-major, coalesced 16B)
    {
        int r = tid >> 1, h = tid & 1;
        int eg = e0 + r;
        int node = eg / KNB;
        int nb = nbrS[r];
        u16* yp = &Y1[r * STR + h * 64];
        const u16* ap = &g_aS[node * CV + h * 64];
        const u16* np = &g_aN[nb * CV + h * 64];
        #pragma unroll
        for (int t4 = 0; t4 < 8; t4++) {
            uint4 yv = *(uint4*)(yp + t4 * 8);
            uint4 av = *(const uint4*)(ap + t4 * 8);
            uint4 nv = *(const uint4*)(np + t4 * 8);
            unsigned* yw = (unsigned*)&yv;
            unsigned* aw = (unsigned*)&av;
            unsigned* nw = (unsigned*)&nv;
            #pragma unroll
            for (int c2 = 0; c2 < 4; c2++) {
                float2 y = __bfloat1622float2(*(__nv_bfloat162*)&yw[c2]);
                float2 a = __bfloat1622float2(*(__nv_bfloat162*)&aw[c2]);
                float2 n = __bfloat1622float2(*(__nv_bfloat162*)&nw[c2]);
                __nv_bfloat162 o = bf2(gelu_f(y.x + a.x + n.x), gelu_f(y.y + a.y + n.y));
                yw[c2] = *(unsigned*)&o;
            }
            *(uint4*)(yp + t4 * 8) = yv;
        }
    }
    // stage W2
    for (int e = tid; e < 128 * 16; e += 256) {
        int n = e >> 4, q = e & 15;
        ((uint4*)&Ws[n * STR])[q] = ((const uint4*)&W2[n * CV])[q];
    }
    __syncthreads();

    // layer 2
    zero_acc(acc);
    #pragma unroll
    for (int ks = 0; ks < 8; ks++)
        mma_step(Y1A + ks * 32, WsB + ks * 32, acc);
    #pragma unroll
    for (int mi = 0; mi < 4; mi++)
        #pragma unroll
        for (int ni = 0; ni < 4; ni++) {
            int r = wr0 + mi * 16 + gr, c = wc0 + ni * 8 + ck;
            float b0v = b2[c], b1v = b2[c + 1];
            *(__nv_bfloat162*)&Y2[r * STR + c] =
                bf2(gelu_f(acc[mi][ni][0] + b0v), gelu_f(acc[mi][ni][1] + b1v));
            *(__nv_bfloat162*)&Y2[(r + 8) * STR + c] =
                bf2(gelu_f(acc[mi][ni][2] + b0v), gelu_f(acc[mi][ni][3] + b1v));
        }
    __syncthreads();
    for (int e = tid; e < 128 * 16; e += 256) {
        int n = e >> 4, q = e & 15;
        ((uint4*)&Ws[n * STR])[q] = ((const uint4*)&W3[n * CV])[q];
    }
    __syncthreads();

    // layer 3 (A = Y2 = Xs base)
    zero_acc(acc);
    #pragma unroll
    for (int ks = 0; ks < 8; ks++)
        mma_step(XsA + ks * 32, WsB + ks * 32, acc);

    if (mode == 0) {
        #pragma unroll
        for (int mi = 0; mi < 4; mi++)
            #pragma unroll
            for (int ni = 0; ni < 4; ni++) {
                int r = wr0 + mi * 16 + gr, c = wc0 + ni * 8 + ck;
                int eg1 = e0 + r, eg2 = e0 + r + 8;
                float b0v = b3[c], b1v = b3[c + 1];
                float ma1 = maskA[eg1], ma2 = maskA[eg2];
                *(__nv_bfloat162*)&g_m[(size_t)eg1 * CV + c] =
                    bf2((acc[mi][ni][0] + b0v) * ma1, (acc[mi][ni][1] + b1v) * ma1);
                *(__nv_bfloat162*)&g_m[(size_t)eg2 * CV + c] =
                    bf2((acc[mi][ni][2] + b0v) * ma2, (acc[mi][ni][3] + b1v) * ma2);
            }
    } else {
        __syncthreads();  // mma reads done before Zf overlay
        #pragma unroll
        for (int mi = 0; mi < 4; mi++)
            #pragma unroll
            for (int ni = 0; ni < 4; ni++) {
                int r = wr0 + mi * 16 + gr, c = wc0 + ni * 8 + ck;
                float b0v = b3[c], b1v = b3[c + 1];
                float2 res1 = *(const float2*)&hEf[(size_t)(e0 + r) * CV + c];
                float2 res2 = *(const float2*)&hEf[(size_t)(e0 + r + 8) * CV + c];
                *(float2*)&Zf[r * Z_STR + c] =
                    make_float2(acc[mi][ni][0] + b0v + res1.x, acc[mi][ni][1] + b1v + res1.y);
                *(float2*)&Zf[(r + 8) * Z_STR + c] =
                    make_float2(acc[mi][ni][2] + b0v + res2.x, acc[mi][ni][3] + b1v + res2.y);
            }
        __syncthreads();
        {
            int r = tid >> 1, h = tid & 1;
            float s = 0.f, sq = 0.f;
            #pragma unroll 8
            for (int c = h * 64; c < h * 64 + 64; c++) {
                float v = Zf[r * Z_STR + c];
                s += v; sq += v * v;
            }
            s  += __shfl_xor_sync(0xffffffffu, s, 1);
            sq += __shfl_xor_sync(0xffffffffu, sq, 1);
            float mean = s * (1.0f / CV);
            float var  = sq * (1.0f / CV) - mean * mean;
            float inv  = rsqrtf(var + LN_EPS);
            size_t eg = (size_t)(e0 + r) * CV;
            for (int c = h * 64; c < h * 64 + 64; c++) {
                float v = Zf[r * Z_STR + c];
                outE[eg + c] = (v - mean) * inv * lnw[c] + lnb[c];
            }
        }
    }
}

// ============================================================
// reduce messages over K, + residual + LN1 -> g_v1
// ============================================================
__global__ void k_red(const float* __restrict__ hV,
                      const float* __restrict__ w, const float* __restrict__ b)
{
    int n = blockIdx.x, t = threadIdx.x;
    const u16* mp = g_m + (size_t)n * KNB * CV + t;
    float s0 = 0.f;
    #pragma unroll
    for (int k = 0; k < KNB; k++)
        s0 += __bfloat162float(*(const __nv_bfloat16*)&mp[k * CV]);
    float x = hV[n * CV + t] + s0 * (1.0f / 30.0f);
    float s = x, sq = x * x;
    #pragma unroll
    for (int o = 16; o > 0; o >>= 1) {
        s  += __shfl_xor_sync(0xffffffffu, s, o);
        sq += __shfl_xor_sync(0xffffffffu, sq, o);
    }
    __shared__ float ss[4], ssq[4];
    int wid = t >> 5, lane = t & 31;
    if (lane == 0) { ss[wid] = s; ssq[wid] = sq; }
    __syncthreads();
    s  = ss[0] + ss[1] + ss[2] + ss[3];
    sq = ssq[0] + ssq[1] + ssq[2] + ssq[3];
    float mean = s * (1.0f / CV);
    float var  = sq * (1.0f / CV) - mean * mean;
    float inv  = rsqrtf(var + LN_EPS);
    g_v1[n * CV + t] = (x - mean) * inv * w[t] + b[t];
}

// ============================================================
// dense1: g_yd = gelu(v1 @ d_w1^T + b1)  [16384, 512]
// ============================================================
__global__ void __launch_bounds__(256, 2)
k_dense1(const float* __restrict__ b)
{
    extern __shared__ char smx[];
    u16* Xs = (u16*)smx;
    u16* Ws = Xs + 128 * STR;
    const int tid = threadIdx.x;
    const int wp = tid >> 5, lane = tid & 31;
    const int wr0 = (wp & 1) * 64, wc0 = (wp >> 1) * 32;
    const int gr = lane >> 2, ck = (lane & 3) * 2;
    const int r0 = blockIdx.x * 128, c0 = blockIdx.y * 128;

    for (int e = tid; e < 128 * 32; e += 256) {
        int r = e >> 5, q = e & 31;
        float4 v = *(const float4*)&g_v1[(r0 + r) * CV + 4 * q];
        __nv_bfloat162 a = bf2(v.x, v.y), bb = bf2(v.z, v.w);
        uint2 o = { *(unsigned*)&a, *(unsigned*)&bb };
        *(uint2*)&Xs[r * STR + 4 * q] = o;
    }
    for (int e = tid; e < 128 * 16; e += 256) {
        int n = e >> 4, q = e & 15;
        ((uint4*)&Ws[n * STR])[q] = ((const uint4*)&g_dw1[(c0 + n) * CV])[q];
    }
    __syncthreads();
    uint32_t aA = smem_u32(Xs) + ldsm_lane_off(lane, wr0);
    uint32_t bA = smem_u32(Ws) + ldsm_lane_off(lane, wc0);
    float acc[4][4][4];
    zero_acc(acc);
    #pragma unroll
    for (int ks = 0; ks < 8; ks++)
        mma_step(aA + ks * 32, bA + ks * 32, acc);
    #pragma unroll
    for (int mi = 0; mi < 4; mi++)
        #pragma unroll
        for (int ni = 0; ni < 4; ni++) {
            int r = wr0 + mi * 16 + gr, cg = c0 + wc0 + ni * 8 + ck;
            float b0v = b[cg], b1v = b[cg + 1];
            *(__nv_bfloat162*)&g_yd[(size_t)(r0 + r) * DW + cg] =
                bf2(gelu_f(acc[mi][ni][0] + b0v), gelu_f(acc[mi][ni][1] + b1v));
            *(__nv_bfloat162*)&g_yd[(size_t)(r0 + r + 8) * DW + cg] =
                bf2(gelu_f(acc[mi][ni][2] + b0v), gelu_f(acc[mi][ni][3] + b1v));
        }
}

// ============================================================
// dense2: z = g_yd @ d_w2^T + b2 + v1; outV = LN2(z) * mask. K=512
// ============================================================
__global__ void __launch_bounds__(256, 2)
k_dense2(const float* __restrict__ b,
         const float* __restrict__ lnw, const float* __restrict__ lnb,
         const float* __restrict__ mask, float* __restrict__ outV)
{
    extern __shared__ char smx[];
    u16* Xs = (u16*)smx;
    u16* Ws = Xs + 128 * STR;
    float* Zf = (float*)smx;
    const int tid = threadIdx.x;
    const int wp = tid >> 5, lane = tid & 31;
    const int wr0 = (wp & 1) * 64, wc0 = (wp >> 1) * 32;
    const int gr = lane >> 2, ck = (lane & 3) * 2;
    const int r0 = blockIdx.x * 128;

    uint32_t aA = smem_u32(Xs) + ldsm_lane_off(lane, wr0);
    uint32_t bA = smem_u32(Ws) + ldsm_lane_off(lane, wc0);
    float acc[4][4][4];
    zero_acc(acc);
    for (int kt = 0; kt < DW; kt += 128) {
        __syncthreads();
        for (int e = tid; e < 128 * 16; e += 256) {
            int r = e >> 4, q = e & 15;
            ((uint4*)&Xs[r * STR])[q] = ((const uint4*)&g_yd[(size_t)(r0 + r) * DW + kt])[q];
        }
        for (int e = tid; e < 128 * 16; e += 256) {
            int n = e >> 4, q = e & 15;
            ((uint4*)&Ws[n * STR])[q] = ((const uint4*)&g_dw2[n * DW + kt])[q];
        }
        __syncthreads();
        #pragma unroll
        for (int ks = 0; ks < 8; ks++)
            mma_step(aA + ks * 32, bA + ks * 32, acc);
    }
    __syncthreads();
    #pragma unroll
    for (int mi = 0; mi < 4; mi++)
        #pragma unroll
        for (int ni = 0; ni < 4; ni++) {
            int r = wr0 + mi * 16 + gr, c = wc0 + ni * 8 + ck;
            float b0v = b[c], b1v = b[c + 1];
            float2 res1 = *(const float2*)&g_v1[(r0 + r) * CV + c];
            float2 res2 = *(const float2*)&g_v1[(r0 + r + 8) * CV + c];
            *(float2*)&Zf[r * Z_STR + c] =
                make_float2(acc[mi][ni][0] + b0v + res1.x, acc[mi][ni][1] + b1v + res1.y);
            *(float2*)&Zf[(r + 8) * Z_STR + c] =
                make_float2(acc[mi][ni][2] + b0v + res2.x, acc[mi][ni][3] + b1v + res2.y);
        }
    __syncthreads();
    {
        int r = tid >> 1, h = tid & 1;
        float s = 0.f, sq = 0.f;
        #pragma unroll 8
        for (int c = h * 64; c < h * 64 + 64; c++) {
            float v = Zf[r * Z_STR + c];
            s += v; sq += v * v;
        }
        s  += __shfl_xor_sync(0xffffffffu, s, 1);
        sq += __shfl_xor_sync(0xffffffffu, sq, 1);
        float mean = s * (1.0f / CV);
        float var  = sq * (1.0f / CV) - mean * mean;
        float inv  = rsqrtf(var + LN_EPS);
        float mk = mask[r0 + r];
        for (int c = h * 64; c < h * 64 + 64; c++) {
            float v = Zf[r * Z_STR + c];
            outV[(r0 + r) * CV + c] = ((v - mean) * inv * lnw[c] + lnb[c]) * mk;
        }
    }
}

// ============================================================
extern "C" void kernel_launch(void* const* d_in, const int* in_sizes, int n_in,
                              void* d_out, int out_size)
{
    (void)in_sizes; (void)n_in; (void)out_size;
    const float* hV    = (const float*)d_in[0];
    const float* hE    = (const float*)d_in[1];
    const int*   nbr   = (const int*)  d_in[2];
    const float* mask  = (const float*)d_in[3];
    const float* maskA = (const float*)d_in[4];
    const float* msg_w1 = (const float*)d_in[5];
    const float* msg_b1 = (const float*)d_in[6];
    const float* msg_w2 = (const float*)d_in[7];
    const float* msg_b2 = (const float*)d_in[8];
    const float* msg_w3 = (const float*)d_in[9];
    const float* msg_b3 = (const float*)d_in[10];
    const float* ln1_w  = (const float*)d_in[11];
    const float* ln1_b  = (const float*)d_in[12];
    const float* d_w1   = (const float*)d_in[13];
    const float* d_b1   = (const float*)d_in[14];
    const float* d_w2   = (const float*)d_in[15];
    const float* d_b2   = (const float*)d_in[16];
    const float* ln2_w  = (const float*)d_in[17];
    const float* ln2_b  = (const float*)d_in[18];
    const float* eu_w1  = (const float*)d_in[19];
    const float* eu_b1  = (const float*)d_in[20];
    const float* eu_w2  = (const float*)d_in[21];
    const float* eu_b2  = (const float*)d_in[22];
    const float* eu_w3  = (const float*)d_in[23];
    const float* eu_b3  = (const float*)d_in[24];
    const float* ln3_w  = (const float*)d_in[25];
    const float* ln3_b  = (const float*)d_in[26];

    float* outV = (float*)d_out;
    float* outE = outV + (size_t)N_NODES * CV;

    u16 *p_w2m, *p_w3m, *p_w2e, *p_w3e, *p_dw1, *p_dw2, *p_w1em, *p_w1ee;
    cudaGetSymbolAddress((void**)&p_w2m, g_w2m);
    cudaGetSymbolAddress((void**)&p_w3m, g_w3m);
    cudaGetSymbolAddress((void**)&p_w2e, g_w2e);
    cudaGetSymbolAddress((void**)&p_w3e, g_w3e);
    cudaGetSymbolAddress((void**)&p_dw1, g_dw1);
    cudaGetSymbolAddress((void**)&p_dw2, g_dw2);
    cudaGetSymbolAddress((void**)&p_w1em, g_w1em);
    cudaGetSymbolAddress((void**)&p_w1ee, g_w1ee);

    const int SMEM_F = 3 * 128 * STR * 2;   // 104448
    const int SMEM_G = 2 * 128 * STR * 2;   // 69632
    cudaFuncSetAttribute(k_fused,   cudaFuncAttributeMaxDynamicSharedMemorySize, SMEM_F);
    cudaFuncSetAttribute(k_nodepre, cudaFuncAttributeMaxDynamicSharedMemorySize, SMEM_G);
    cudaFuncSetAttribute(k_dense1,  cudaFuncAttributeMaxDynamicSharedMemorySize, SMEM_G);
    cudaFuncSetAttribute(k_dense2,  cudaFuncAttributeMaxDynamicSharedMemorySize, SMEM_G);

    // weight conversions
    k_cvt<<<16, 256>>>(msg_w2, p_w2m, 4096);
    k_cvt<<<16, 256>>>(msg_w3, p_w3m, 4096);
    k_cvt<<<16, 256>>>(eu_w2, p_w2e, 4096);
    k_cvt<<<16, 256>>>(eu_w3, p_w3e, 4096);
    k_cvt<<<64, 256>>>(d_w1, p_dw1, 16384);
    k_cvt<<<64, 256>>>(d_w2, p_dw2, 16384);
    k_cvt_w1e<<<64, 256>>>(msg_w1, p_w1em);
    k_cvt_w1e<<<64, 256>>>(eu_w1, p_w1ee);

    const int EGRID = EDGES / 128;  // 6144

    // message phase
    k_nodepre<<<dim3(N_NODES / 128, 2), 256, SMEM_G>>>(hV, msg_w1, msg_b1);
    k_fused<<<EGRID, 256, SMEM_F>>>(hE, nbr, p_w1em, p_w2m, p_w3m,
                                    msg_b2, msg_b3, maskA, ln3_w, ln3_b, outE, 0);
    k_red<<<N_NODES, 128>>>(hV, ln1_w, ln1_b);
    // dense phase
    k_dense1<<<dim3(N_NODES / 128, 4), 256, SMEM_G>>>(d_b1);
    k_dense2<<<N_NODES / 128, 256, SMEM_G>>>(d_b2, ln2_w, ln2_b, mask, outV);
    // edge update phase
    k_nodepre<<<dim3(N_NODES / 128, 2), 256, SMEM_G>>>(outV, eu_w1, eu_b1);
    k_fused<<<EGRID, 256, SMEM_F>>>(hE, nbr, p_w1ee, p_w2e, p_w3e,
                                    eu_b2, eu_b3, maskA, ln3_w, ln3_b, outE, 1);
}

// round 9
// speedup vs baseline: 9.5216x; 1.1557x over previous
#include <cuda_runtime.h>
#include <cuda_bf16.h>
#include <cstdint>

#define N_NODES 16384
#define KNB 48
#define EDGES (N_NODES * KNB)
#define CV 128
#define IN_DIM 384
#define DW 512
#define LN_EPS 1e-5f

#define STR 136                 // bf16 units; 272B row -> LDSM conflict-free
#define Z_STR 132
#define TBYTES (128 * STR * 2)  // 34816 bytes per tile

typedef unsigned short u16;

// ---------- scratch (allocation-free) ----------
__device__ u16  g_m[(size_t)EDGES * CV];
__device__ u16  g_aS[N_NODES * CV];
__device__ u16  g_aN[N_NODES * CV];
__device__ float g_v1[N_NODES * CV];
__device__ u16  g_yd[(size_t)N_NODES * DW];
__device__ u16 g_w1em[CV * CV], g_w2m[CV * CV], g_w3m[CV * CV];
__device__ u16 g_w1ee[CV * CV], g_w2e[CV * CV], g_w3e[CV * CV];
__device__ u16 g_dw1[DW * CV], g_dw2[CV * DW];

// ---------- helpers ----------
__device__ __forceinline__ float gelu_f(float x) {
    float y = 0.79788456080286536f * x * (1.0f + 0.044715f * x * x);
    float t; asm("tanh.approx.f32 %0, %1;" : "=f"(t) : "f"(y));
    return 0.5f * x * (1.0f + t);
}
__device__ __forceinline__ __nv_bfloat162 bf2(float a, float b) {
    return __floats2bfloat162_rn(a, b);
}
__device__ __forceinline__ uint32_t smem_u32(const void* p) {
    uint32_t a;
    asm("{ .reg .u64 t; cvta.to.shared.u64 t, %1; cvt.u32.u64 %0, t; }" : "=r"(a) : "l"(p));
    return a;
}
__device__ __forceinline__ void cp16(uint32_t dst, const void* src) {
    asm volatile("cp.async.cg.shared.global [%0], [%1], 16;" :: "r"(dst), "l"(src));
}
#define CP_COMMIT() asm volatile("cp.async.commit_group;")
#define CP_WAIT(n)  asm volatile("cp.async.wait_group %0;" :: "n"(n))

__device__ __forceinline__ void mma16816(float d[4], const unsigned a[4], const unsigned b[2]) {
    asm volatile(
        "mma.sync.aligned.m16n8k16.row.col.f32.bf16.bf16.f32 "
        "{%0,%1,%2,%3}, {%4,%5,%6,%7}, {%8,%9}, {%0,%1,%2,%3};"
        : "+f"(d[0]), "+f"(d[1]), "+f"(d[2]), "+f"(d[3])
        : "r"(a[0]), "r"(a[1]), "r"(a[2]), "r"(a[3]), "r"(b[0]), "r"(b[1]));
}
__device__ __forceinline__ void ldsm4(unsigned& r0, unsigned& r1, unsigned& r2, unsigned& r3,
                                      uint32_t addr) {
    asm volatile("ldmatrix.sync.aligned.m8n8.x4.shared.b16 {%0,%1,%2,%3}, [%4];"
                 : "=r"(r0), "=r"(r1), "=r"(r2), "=r"(r3) : "r"(addr));
}
// one k16 step for a 64x32 warp tile (addresses carry lane offsets)
__device__ __forceinline__ void mma_step(uint32_t aAddr, uint32_t bAddr, float acc[4][4][4]) {
    unsigned a[4][4], b[4][2];
    #pragma unroll
    for (int mi = 0; mi < 4; mi++)
        ldsm4(a[mi][0], a[mi][1], a[mi][2], a[mi][3], aAddr + mi * (16 * STR * 2));
    #pragma unroll
    for (int np = 0; np < 2; np++) {
        unsigned r0, r1, r2, r3;
        ldsm4(r0, r1, r2, r3, bAddr + np * (16 * STR * 2));
        b[2 * np][0] = r0;     b[2 * np][1] = r2;
        b[2 * np + 1][0] = r1; b[2 * np + 1][1] = r3;
    }
    #pragma unroll
    for (int mi = 0; mi < 4; mi++)
        #pragma unroll
        for (int ni = 0; ni < 4; ni++)
            mma16816(acc[mi][ni], a[mi], b[ni]);
}
__device__ __forceinline__ void zero_acc(float acc[4][4][4]) {
    #pragma unroll
    for (int mi = 0; mi < 4; mi++)
        #pragma unroll
        for (int ni = 0; ni < 4; ni++)
            #pragma unroll
            for (int k = 0; k < 4; k++) acc[mi][ni][k] = 0.f;
}
__device__ __forceinline__ uint32_t ldsm_lane_off(int lane, int tile0) {
    return (uint32_t)(((tile0 + (lane & 15)) * STR + ((lane >> 4) << 3)) * 2);
}
// stage a 128x128 bf16 W tile into smem via cp.async
__device__ __forceinline__ void stage_w_async(uint32_t dstBase, const u16* __restrict__ W, int tid) {
    #pragma unroll
    for (int e = tid; e < 2048; e += 256) {
        int n = e >> 4, q = e & 15;
        cp16(dstBase + (uint32_t)(n * STR + q * 8) * 2, W + n * CV + q * 8);
    }
}

// ============================================================
// prep conversions (3 launches total)
// ============================================================
__global__ void k_cvt3(const float* __restrict__ s2, const float* __restrict__ s3,
                       const float* __restrict__ s1full,
                       u16* __restrict__ d2, u16* __restrict__ d3, u16* __restrict__ d1e)
{
    int i = blockIdx.x * 256 + threadIdx.x;      // 3*16384
    int seg = i >> 14, j = i & 16383;
    if (seg == 0)      d2[j] = __bfloat16_as_ushort(__float2bfloat16(s2[j]));
    else if (seg == 1) d3[j] = __bfloat16_as_ushort(__float2bfloat16(s3[j]));
    else {
        int o = j >> 7, c = j & 127;
        d1e[j] = __bfloat16_as_ushort(__float2bfloat16(s1full[o * IN_DIM + CV + c]));
    }
}
__global__ void k_cvtd(const float* __restrict__ w1, const float* __restrict__ w2)
{
    int i = blockIdx.x * 256 + threadIdx.x;      // 2*65536
    if (i < 65536) g_dw1[i] = __bfloat16_as_ushort(__float2bfloat16(w1[i]));
    else           g_dw2[i - 65536] = __bfloat16_as_ushort(__float2bfloat16(w2[i - 65536]));
}

// ============================================================
// node precompute: aS = W_self @ hV + b1 (cg=0), aN = W_nbr @ hV (cg=1)
// ============================================================
__global__ void __launch_bounds__(256, 2)
k_nodepre(const float* __restrict__ hVsrc, const float* __restrict__ w1,
          const float* __restrict__ b1, int cg)
{
    extern __shared__ char smx[];
    u16* Xs = (u16*)smx;
    u16* Ws = Xs + 128 * STR;
    const int tid = threadIdx.x;
    const int wp = tid >> 5, lane = tid & 31;
    const int wr0 = (wp & 1) * 64, wc0 = (wp >> 1) * 32;
    const int gr = lane >> 2, ck = (lane & 3) * 2;
    const int r0 = blockIdx.x * 128;
    const int koff = cg ? 2 * CV : 0;
    u16* dst = cg ? g_aN : g_aS;

    for (int e = tid; e < 128 * 32; e += 256) {
        int r = e >> 5, q = e & 31;
        float4 v = *(const float4*)&hVsrc[(r0 + r) * CV + 4 * q];
        __nv_bfloat162 a = bf2(v.x, v.y), b = bf2(v.z, v.w);
        uint2 o = { *(unsigned*)&a, *(unsigned*)&b };
        *(uint2*)&Xs[r * STR + 4 * q] = o;
    }
    for (int e = tid; e < 128 * 32; e += 256) {
        int n = e >> 5, q = e & 31;
        float4 v = *(const float4*)&w1[n * IN_DIM + koff + 4 * q];
        __nv_bfloat162 a = bf2(v.x, v.y), b = bf2(v.z, v.w);
        uint2 o = { *(unsigned*)&a, *(unsigned*)&b };
        *(uint2*)&Ws[n * STR + 4 * q] = o;
    }
    __syncthreads();
    uint32_t aA = smem_u32(Xs) + ldsm_lane_off(lane, wr0);
    uint32_t bA = smem_u32(Ws) + ldsm_lane_off(lane, wc0);
    float acc[4][4][4];
    zero_acc(acc);
    #pragma unroll
    for (int ks = 0; ks < 8; ks++)
        mma_step(aA + ks * 32, bA + ks * 32, acc);
    #pragma unroll
    for (int mi = 0; mi < 4; mi++)
        #pragma unroll
        for (int ni = 0; ni < 4; ni++) {
            int r = wr0 + mi * 16 + gr, c = wc0 + ni * 8 + ck;
            float b0v = cg ? 0.f : b1[c], b1v = cg ? 0.f : b1[c + 1];
            *(__nv_bfloat162*)&dst[(r0 + r) * CV + c] = bf2(acc[mi][ni][0] + b0v, acc[mi][ni][1] + b1v);
            *(__nv_bfloat162*)&dst[(r0 + r + 8) * CV + c] = bf2(acc[mi][ni][2] + b0v, acc[mi][ni][3] + b1v);
        }
}

// ============================================================
// Fused 3-layer MLP, 128 edge rows/block, 3-buffer W prefetch.
// A lives in B0 throughout; W alternates B1/B2 via cp.async.
// ============================================================
__global__ void __launch_bounds__(256, 2)
k_fused(const float* __restrict__ hEf, const int* __restrict__ nbr,
        const u16* __restrict__ W1e, const u16* __restrict__ W2, const u16* __restrict__ W3,
        const float* __restrict__ b2, const float* __restrict__ b3,
        const float* __restrict__ maskA,
        const float* __restrict__ lnw, const float* __restrict__ lnb,
        float* __restrict__ outE, int mode)
{
    extern __shared__ char sm[];
    u16* B0 = (u16*)sm;                  // A (all layers)
    float* Zf = (float*)(sm + TBYTES);   // mode-1 overlay of B1+B2
    __shared__ int nbrS[128];

    const int tid = threadIdx.x;
    const int wp = tid >> 5, lane = tid & 31;
    const int wr0 = (wp & 1) * 64, wc0 = (wp >> 1) * 32;
    const int gr = lane >> 2, ck = (lane & 3) * 2;
    const int e0 = blockIdx.x * 128;

    const uint32_t smb = smem_u32(sm);
    const uint32_t A_addr  = smb + ldsm_lane_off(lane, wr0);
    const uint32_t B1_addr = smb + TBYTES + ldsm_lane_off(lane, wc0);
    const uint32_t B2_addr = smb + 2 * TBYTES + ldsm_lane_off(lane, wc0);

    // W1 -> B1 (g1), W2 -> B2 (g2), async
    stage_w_async(smb + TBYTES, W1e, tid);
    CP_COMMIT();
    stage_w_async(smb + 2 * TBYTES, W2, tid);
    CP_COMMIT();

    // X: hE fp32 -> bf16 -> B0
    #pragma unroll
    for (int e = tid; e < 128 * 16; e += 256) {
        int r = e >> 4, q = e & 15;
        const float4* src = (const float4*)&hEf[(size_t)(e0 + r) * CV + q * 8];
        float4 v0 = src[0], v1 = src[1];
        __nv_bfloat162 p0 = bf2(v0.x, v0.y), p1 = bf2(v0.z, v0.w);
        __nv_bfloat162 p2 = bf2(v1.x, v1.y), p3 = bf2(v1.z, v1.w);
        uint4 o = { *(unsigned*)&p0, *(unsigned*)&p1, *(unsigned*)&p2, *(unsigned*)&p3 };
        *(uint4*)&B0[r * STR + q * 8] = o;
    }
    if (tid < 128) nbrS[tid] = nbr[e0 + tid];
    CP_WAIT(1);            // W1 arrived
    __syncthreads();

    // ---- layer 1 ----
    float acc[4][4][4];
    zero_acc(acc);
    #pragma unroll
    for (int ks = 0; ks < 8; ks++)
        mma_step(A_addr + ks * 32, B1_addr + ks * 32, acc);
    __syncthreads();       // all reads of B0/B1 done

    // epi1 (fragment layout): gelu(acc + aS[node] + aN[nbr]) -> B0
    {
        uint32_t offS[8], offN[8];
        #pragma unroll
        for (int mi = 0; mi < 4; mi++)
            #pragma unroll
            for (int hh = 0; hh < 2; hh++) {
                int r = wr0 + mi * 16 + gr + hh * 8;
                int j = mi * 2 + hh;
                offS[j] = (uint32_t)(((e0 + r) / KNB) * CV) * 2;
                offN[j] = (uint32_t)(nbrS[r] * CV) * 2;
            }
        const char* aSb = (const char*)g_aS;
        const char* aNb = (const char*)g_aN;
        #pragma unroll
        for (int mi = 0; mi < 4; mi++)
            #pragma unroll
            for (int ni = 0; ni < 4; ni++) {
                int c = wc0 + ni * 8 + ck;
                #pragma unroll
                for (int hh = 0; hh < 2; hh++) {
                    int j = mi * 2 + hh;
                    unsigned as = *(const unsigned*)(aSb + offS[j] + c * 2);
                    unsigned an = *(const unsigned*)(aNb + offN[j] + c * 2);
                    float2 a = __bfloat1622float2(*(__nv_bfloat162*)&as);
                    float2 n = __bfloat1622float2(*(__nv_bfloat162*)&an);
                    float v0 = acc[mi][ni][2 * hh]     + a.x + n.x;
                    float v1 = acc[mi][ni][2 * hh + 1] + a.y + n.y;
                    int r = wr0 + mi * 16 + gr + hh * 8;
                    *(__nv_bfloat162*)&B0[r * STR + c] = bf2(gelu_f(v0), gelu_f(v1));
                }
            }
    }
    stage_w_async(smb + TBYTES, W3, tid);   // B1 free -> W3 (g3)
    CP_COMMIT();
    CP_WAIT(1);            // W2 arrived
    __syncthreads();

    // ---- layer 2 ----
    zero_acc(acc);
    #pragma unroll
    for (int ks = 0; ks < 8; ks++)
        mma_step(A_addr + ks * 32, B2_addr + ks * 32, acc);
    __syncthreads();
    // epi2: gelu(acc + b2) -> B0
    #pragma unroll
    for (int mi = 0; mi < 4; mi++)
        #pragma unroll
        for (int ni = 0; ni < 4; ni++) {
            int r = wr0 + mi * 16 + gr, c = wc0 + ni * 8 + ck;
            float b0v = b2[c], b1v = b2[c + 1];
            *(__nv_bfloat162*)&B0[r * STR + c] =
                bf2(gelu_f(acc[mi][ni][0] + b0v), gelu_f(acc[mi][ni][1] + b1v));
            *(__nv_bfloat162*)&B0[(r + 8) * STR + c] =
                bf2(gelu_f(acc[mi][ni][2] + b0v), gelu_f(acc[mi][ni][3] + b1v));
        }
    CP_WAIT(0);            // W3 arrived
    __syncthreads();

    // ---- layer 3 ----
    zero_acc(acc);
    #pragma unroll
    for (int ks = 0; ks < 8; ks++)
        mma_step(A_addr + ks * 32, B1_addr + ks * 32, acc);

    if (mode == 0) {
        #pragma unroll
        for (int mi = 0; mi < 4; mi++)
            #pragma unroll
            for (int ni = 0; ni < 4; ni++) {
                int r = wr0 + mi * 16 + gr, c = wc0 + ni * 8 + ck;
                int eg1 = e0 + r, eg2 = e0 + r + 8;
                float b0v = b3[c], b1v = b3[c + 1];
                float ma1 = maskA[eg1], ma2 = maskA[eg2];
                *(__nv_bfloat162*)&g_m[(size_t)eg1 * CV + c] =
                    bf2((acc[mi][ni][0] + b0v) * ma1, (acc[mi][ni][1] + b1v) * ma1);
                *(__nv_bfloat162*)&g_m[(size_t)eg2 * CV + c] =
                    bf2((acc[mi][ni][2] + b0v) * ma2, (acc[mi][ni][3] + b1v) * ma2);
            }
    } else {
        __syncthreads();   // B1 reads done before Zf overlay
        #pragma unroll
        for (int mi = 0; mi < 4; mi++)
            #pragma unroll
            for (int ni = 0; ni < 4; ni++) {
                int r = wr0 + mi * 16 + gr, c = wc0 + ni * 8 + ck;
                float b0v = b3[c], b1v = b3[c + 1];
                float2 res1 = *(const float2*)&hEf[(size_t)(e0 + r) * CV + c];
                float2 res2 = *(const float2*)&hEf[(size_t)(e0 + r + 8) * CV + c];
                *(float2*)&Zf[r * Z_STR + c] =
                    make_float2(acc[mi][ni][0] + b0v + res1.x, acc[mi][ni][1] + b1v + res1.y);
                *(float2*)&Zf[(r + 8) * Z_STR + c] =
                    make_float2(acc[mi][ni][2] + b0v + res2.x, acc[mi][ni][3] + b1v + res2.y);
            }
        __syncthreads();
        {
            int r = tid >> 1, h = tid & 1;
            float s = 0.f, sq = 0.f;
            #pragma unroll 8
            for (int c = h * 64; c < h * 64 + 64; c++) {
                float v = Zf[r * Z_STR + c];
                s += v; sq += v * v;
            }
            s  += __shfl_xor_sync(0xffffffffu, s, 1);
            sq += __shfl_xor_sync(0xffffffffu, sq, 1);
            float mean = s * (1.0f / CV);
            float var  = sq * (1.0f / CV) - mean * mean;
            float inv  = rsqrtf(var + LN_EPS);
            size_t eg = (size_t)(e0 + r) * CV;
            for (int c = h * 64; c < h * 64 + 64; c++) {
                float v = Zf[r * Z_STR + c];
                outE[eg + c] = (v - mean) * inv * lnw[c] + lnb[c];
            }
        }
    }
}

// ============================================================
// reduce messages over K, + residual + LN1 -> g_v1
// ============================================================
__global__ void k_red(const float* __restrict__ hV,
                      const float* __restrict__ w, const float* __restrict__ b)
{
    int n = blockIdx.x, t = threadIdx.x;
    const u16* mp = g_m + (size_t)n * KNB * CV + t;
    float s0 = 0.f;
    #pragma unroll
    for (int k = 0; k < KNB; k++)
        s0 += __bfloat162float(*(const __nv_bfloat16*)&mp[k * CV]);
    float x = hV[n * CV + t] + s0 * (1.0f / 30.0f);
    float s = x, sq = x * x;
    #pragma unroll
    for (int o = 16; o > 0; o >>= 1) {
        s  += __shfl_xor_sync(0xffffffffu, s, o);
        sq += __shfl_xor_sync(0xffffffffu, sq, o);
    }
    __shared__ float ss[4], ssq[4];
    int wid = t >> 5, lane = t & 31;
    if (lane == 0) { ss[wid] = s; ssq[wid] = sq; }
    __syncthreads();
    s  = ss[0] + ss[1] + ss[2] + ss[3];
    sq = ssq[0] + ssq[1] + ssq[2] + ssq[3];
    float mean = s * (1.0f / CV);
    float var  = sq * (1.0f / CV) - mean * mean;
    float inv  = rsqrtf(var + LN_EPS);
    g_v1[n * CV + t] = (x - mean) * inv * w[t] + b[t];
}

// ============================================================
// dense1: g_yd = gelu(v1 @ d_w1^T + b1)  [16384, 512]
// ============================================================
__global__ void __launch_bounds__(256, 2)
k_dense1(const float* __restrict__ b)
{
    extern __shared__ char smx[];
    u16* Xs = (u16*)smx;
    const uint32_t smb = smem_u32(smx);
    const int tid = threadIdx.x;
    const int wp = tid >> 5, lane = tid & 31;
    const int wr0 = (wp & 1) * 64, wc0 = (wp >> 1) * 32;
    const int gr = lane >> 2, ck = (lane & 3) * 2;
    const int r0 = blockIdx.x * 128, c0 = blockIdx.y * 128;

    stage_w_async(smb + TBYTES, &g_dw1[c0 * CV], tid);
    CP_COMMIT();
    for (int e = tid; e < 128 * 32; e += 256) {
        int r = e >> 5, q = e & 31;
        float4 v = *(const float4*)&g_v1[(r0 + r) * CV + 4 * q];
        __nv_bfloat162 a = bf2(v.x, v.y), bb = bf2(v.z, v.w);
        uint2 o = { *(unsigned*)&a, *(unsigned*)&bb };
        *(uint2*)&Xs[r * STR + 4 * q] = o;
    }
    CP_WAIT(0);
    __syncthreads();
    uint32_t aA = smb + ldsm_lane_off(lane, wr0);
    uint32_t bA = smb + TBYTES + ldsm_lane_off(lane, wc0);
    float acc[4][4][4];
    zero_acc(acc);
    #pragma unroll
    for (int ks = 0; ks < 8; ks++)
        mma_step(aA + ks * 32, bA + ks * 32, acc);
    #pragma unroll
    for (int mi = 0; mi < 4; mi++)
        #pragma unroll
        for (int ni = 0; ni < 4; ni++) {
            int r = wr0 + mi * 16 + gr, cg = c0 + wc0 + ni * 8 + ck;
            float b0v = b[cg], b1v = b[cg + 1];
            *(__nv_bfloat162*)&g_yd[(size_t)(r0 + r) * DW + cg] =
                bf2(gelu_f(acc[mi][ni][0] + b0v), gelu_f(acc[mi][ni][1] + b1v));
            *(__nv_bfloat162*)&g_yd[(size_t)(r0 + r + 8) * DW + cg] =
                bf2(gelu_f(acc[mi][ni][2] + b0v), gelu_f(acc[mi][ni][3] + b1v));
        }
}

// ============================================================
// dense2: double-buffered cp.async K-chunks; + residual + LN2 + mask
// ============================================================
__device__ __forceinline__ void d2_stage(uint32_t pairBase, int r0, int kt, int tid) {
    #pragma unroll
    for (int e = tid; e < 2048; e += 256) {
        int r = e >> 4, q = e & 15;
        cp16(pairBase + (uint32_t)(r * STR + q * 8) * 2,
             &g_yd[(size_t)(r0 + r) * DW + kt + q * 8]);
    }
    #pragma unroll
    for (int e = tid; e < 2048; e += 256) {
        int n = e >> 4, q = e & 15;
        cp16(pairBase + TBYTES + (uint32_t)(n * STR + q * 8) * 2,
             &g_dw2[n * DW + kt + q * 8]);
    }
    CP_COMMIT();
}

__global__ void __launch_bounds__(256, 1)
k_dense2(const float* __restrict__ b,
         const float* __restrict__ lnw, const float* __restrict__ lnb,
         const float* __restrict__ mask, float* __restrict__ outV)
{
    extern __shared__ char smx[];
    float* Zf = (float*)smx;
    const uint32_t smb = smem_u32(smx);
    const int tid = threadIdx.x;
    const int wp = tid >> 5, lane = tid & 31;
    const int wr0 = (wp & 1) * 64, wc0 = (wp >> 1) * 32;
    const int gr = lane >> 2, ck = (lane & 3) * 2;
    const int r0 = blockIdx.x * 128;

    float acc[4][4][4];
    zero_acc(acc);
    d2_stage(smb, r0, 0, tid);
    #pragma unroll
    for (int i = 0; i < 4; i++) {
        if (i < 3) d2_stage(smb + ((i + 1) & 1) * 2 * TBYTES, r0, (i + 1) * 128, tid);
        if (i < 3) { CP_WAIT(1); } else { CP_WAIT(0); }
        __syncthreads();
        uint32_t pb = smb + (i & 1) * 2 * TBYTES;
        uint32_t aA = pb + ldsm_lane_off(lane, wr0);
        uint32_t bA = pb + TBYTES + ldsm_lane_off(lane, wc0);
        #pragma unroll
        for (int ks = 0; ks < 8; ks++)
            mma_step(aA + ks * 32, bA + ks * 32, acc);
        __syncthreads();
    }
    #pragma unroll
    for (int mi = 0; mi < 4; mi++)
        #pragma unroll
        for (int ni = 0; ni < 4; ni++) {
            int r = wr0 + mi * 16 + gr, c = wc0 + ni * 8 + ck;
            float b0v = b[c], b1v = b[c + 1];
            float2 res1 = *(const float2*)&g_v1[(r0 + r) * CV + c];
            float2 res2 = *(const float2*)&g_v1[(r0 + r + 8) * CV + c];
            *(float2*)&Zf[r * Z_STR + c] =
                make_float2(acc[mi][ni][0] + b0v + res1.x, acc[mi][ni][1] + b1v + res1.y);
            *(float2*)&Zf[(r + 8) * Z_STR + c] =
                make_float2(acc[mi][ni][2] + b0v + res2.x, acc[mi][ni][3] + b1v + res2.y);
        }
    __syncthreads();
    {
        int r = tid >> 1, h = tid & 1;
        float s = 0.f, sq = 0.f;
        #pragma unroll 8
        for (int c = h * 64; c < h * 64 + 64; c++) {
            float v = Zf[r * Z_STR + c];
            s += v; sq += v * v;
        }
        s  += __shfl_xor_sync(0xffffffffu, s, 1);
        sq += __shfl_xor_sync(0xffffffffu, sq, 1);
        float mean = s * (1.0f / CV);
        float var  = sq * (1.0f / CV) - mean * mean;
        float inv  = rsqrtf(var + LN_EPS);
        float mk = mask[r0 + r];
        for (int c = h * 64; c < h * 64 + 64; c++) {
            float v = Zf[r * Z_STR + c];
            outV[(r0 + r) * CV + c] = ((v - mean) * inv * lnw[c] + lnb[c]) * mk;
        }
    }
}

// ============================================================
extern "C" void kernel_launch(void* const* d_in, const int* in_sizes, int n_in,
                              void* d_out, int out_size)
{
    (void)in_sizes; (void)n_in; (void)out_size;
    const float* hV    = (const float*)d_in[0];
    const float* hE    = (const float*)d_in[1];
    const int*   nbr   = (const int*)  d_in[2];
    const float* mask  = (const float*)d_in[3];
    const float* maskA = (const float*)d_in[4];
    const float* msg_w1 = (const float*)d_in[5];
    const float* msg_b1 = (const float*)d_in[6];
    const float* msg_w2 = (const float*)d_in[7];
    const float* msg_b2 = (const float*)d_in[8];
    const float* msg_w3 = (const float*)d_in[9];
    const float* msg_b3 = (const float*)d_in[10];
    const float* ln1_w  = (const float*)d_in[11];
    const float* ln1_b  = (const float*)d_in[12];
    const float* d_w1   = (const float*)d_in[13];
    const float* d_b1   = (const float*)d_in[14];
    const float* d_w2   = (const float*)d_in[15];
    const float* d_b2   = (const float*)d_in[16];
    const float* ln2_w  = (const float*)d_in[17];
    const float* ln2_b  = (const float*)d_in[18];
    const float* eu_w1  = (const float*)d_in[19];
    const float* eu_b1  = (const float*)d_in[20];
    const float* eu_w2  = (const float*)d_in[21];
    const float* eu_b2  = (const float*)d_in[22];
    const float* eu_w3  = (const float*)d_in[23];
    const float* eu_b3  = (const float*)d_in[24];
    const float* ln3_w  = (const float*)d_in[25];
    const float* ln3_b  = (const float*)d_in[26];

    float* outV = (float*)d_out;
    float* outE = outV + (size_t)N_NODES * CV;

    u16 *p_w2m, *p_w3m, *p_w2e, *p_w3e, *p_w1em, *p_w1ee;
    cudaGetSymbolAddress((void**)&p_w2m, g_w2m);
    cudaGetSymbolAddress((void**)&p_w3m, g_w3m);
    cudaGetSymbolAddress((void**)&p_w2e, g_w2e);
    cudaGetSymbolAddress((void**)&p_w3e, g_w3e);
    cudaGetSymbolAddress((void**)&p_w1em, g_w1em);
    cudaGetSymbolAddress((void**)&p_w1ee, g_w1ee);

    const int SMEM_F  = 3 * TBYTES;   // 104448
    const int SMEM_G  = 2 * TBYTES;   // 69632
    const int SMEM_D2 = 4 * TBYTES;   // 139264
    cudaFuncSetAttribute(k_fused,   cudaFuncAttributeMaxDynamicSharedMemorySize, SMEM_F);
    cudaFuncSetAttribute(k_nodepre, cudaFuncAttributeMaxDynamicSharedMemorySize, SMEM_G);
    cudaFuncSetAttribute(k_dense1,  cudaFuncAttributeMaxDynamicSharedMemorySize, SMEM_G);
    cudaFuncSetAttribute(k_dense2,  cudaFuncAttributeMaxDynamicSharedMemorySize, SMEM_D2);

    const int EGRID = EDGES / 128;  // 6144

    // launches 1-5 (prep) so launch #6 = k_fused for the ncu window
    k_cvt3<<<192, 256>>>(msg_w2, msg_w3, msg_w1, p_w2m, p_w3m, p_w1em);   // 1
    k_cvt3<<<192, 256>>>(eu_w2,  eu_w3,  eu_w1,  p_w2e, p_w3e, p_w1ee);   // 2
    k_cvtd<<<512, 256>>>(d_w1, d_w2);                                     // 3
    k_nodepre<<<N_NODES / 128, 256, SMEM_G>>>(hV, msg_w1, msg_b1, 0);     // 4
    k_nodepre<<<N_NODES / 128, 256, SMEM_G>>>(hV, msg_w1, msg_b1, 1);     // 5
    k_fused<<<EGRID, 256, SMEM_F>>>(hE, nbr, p_w1em, p_w2m, p_w3m,        // 6 <- profiled
                                    msg_b2, msg_b3, maskA, ln3_w, ln3_b, outE, 0);
    k_red<<<N_NODES, 128>>>(hV, ln1_w, ln1_b);
    k_dense1<<<dim3(N_NODES / 128, 4), 256, SMEM_G>>>(d_b1);
    k_dense2<<<N_NODES / 128, 256, SMEM_D2>>>(d_b2, ln2_w, ln2_b, mask, outV);
    k_nodepre<<<N_NODES / 128, 256, SMEM_G>>>(outV, eu_w1, eu_b1, 0);
    k_nodepre<<<N_NODES / 128, 256, SMEM_G>>>(outV, eu_w1, eu_b1, 1);
    k_fused<<<EGRID, 256, SMEM_F>>>(hE, nbr, p_w1ee, p_w2e, p_w3e,
                                    eu_b2, eu_b3, maskA, ln3_w, ln3_b, outE, 1);
}

// round 10
// speedup vs baseline: 10.2613x; 1.0777x over previous
#include <cuda_runtime.h>
#include <cuda_bf16.h>
#include <cstdint>

#define N_NODES 16384
#define KNB 48
#define EDGES (N_NODES * KNB)
#define CV 128
#define IN_DIM 384
#define DW 512
#define LN_EPS 1e-5f

#define STR 136                 // bf16 units; 272B row -> LDSM conflict-free
#define Z_STR 132
#define TBYTES (128 * STR * 2)  // 34816 bytes per tile

typedef unsigned short u16;

// ---------- scratch (allocation-free) ----------
__device__ float g_Spart[(size_t)2 * N_NODES * CV];  // per-(node,slot) partial sums, fp32
__device__ u16  g_aS[N_NODES * CV];
__device__ u16  g_aN[N_NODES * CV];
__device__ float g_v1[N_NODES * CV];
__device__ u16  g_yd[(size_t)N_NODES * DW];
__device__ u16 g_w1em[CV * CV], g_w2m[CV * CV], g_w3m[CV * CV];
__device__ u16 g_w1ee[CV * CV], g_w2e[CV * CV], g_w3e[CV * CV];
__device__ u16 g_dw1[DW * CV], g_dw2[CV * DW];

// ---------- helpers ----------
__device__ __forceinline__ float gelu_f(float x) {
    float y = 0.79788456080286536f * x * (1.0f + 0.044715f * x * x);
    float t; asm("tanh.approx.f32 %0, %1;" : "=f"(t) : "f"(y));
    return 0.5f * x * (1.0f + t);
}
__device__ __forceinline__ __nv_bfloat162 bf2(float a, float b) {
    return __floats2bfloat162_rn(a, b);
}
__device__ __forceinline__ uint32_t smem_u32(const void* p) {
    uint32_t a;
    asm("{ .reg .u64 t; cvta.to.shared.u64 t, %1; cvt.u32.u64 %0, t; }" : "=r"(a) : "l"(p));
    return a;
}
__device__ __forceinline__ void cp16(uint32_t dst, const void* src) {
    asm volatile("cp.async.cg.shared.global [%0], [%1], 16;" :: "r"(dst), "l"(src));
}
#define CP_COMMIT() asm volatile("cp.async.commit_group;")
#define CP_WAIT(n)  asm volatile("cp.async.wait_group %0;" :: "n"(n))

__device__ __forceinline__ void mma16816(float d[4], const unsigned a[4], const unsigned b[2]) {
    asm volatile(
        "mma.sync.aligned.m16n8k16.row.col.f32.bf16.bf16.f32 "
        "{%0,%1,%2,%3}, {%4,%5,%6,%7}, {%8,%9}, {%0,%1,%2,%3};"
        : "+f"(d[0]), "+f"(d[1]), "+f"(d[2]), "+f"(d[3])
        : "r"(a[0]), "r"(a[1]), "r"(a[2]), "r"(a[3]), "r"(b[0]), "r"(b[1]));
}
__device__ __forceinline__ void ldsm4(unsigned& r0, unsigned& r1, unsigned& r2, unsigned& r3,
                                      uint32_t addr) {
    asm volatile("ldmatrix.sync.aligned.m8n8.x4.shared.b16 {%0,%1,%2,%3}, [%4];"
                 : "=r"(r0), "=r"(r1), "=r"(r2), "=r"(r3) : "r"(addr));
}
__device__ __forceinline__ void mma_step(uint32_t aAddr, uint32_t bAddr, float acc[4][4][4]) {
    unsigned a[4][4], b[4][2];
    #pragma unroll
    for (int mi = 0; mi < 4; mi++)
        ldsm4(a[mi][0], a[mi][1], a[mi][2], a[mi][3], aAddr + mi * (16 * STR * 2));
    #pragma unroll
    for (int np = 0; np < 2; np++) {
        unsigned r0, r1, r2, r3;
        ldsm4(r0, r1, r2, r3, bAddr + np * (16 * STR * 2));
        b[2 * np][0] = r0;     b[2 * np][1] = r2;
        b[2 * np + 1][0] = r1; b[2 * np + 1][1] = r3;
    }
    #pragma unroll
    for (int mi = 0; mi < 4; mi++)
        #pragma unroll
        for (int ni = 0; ni < 4; ni++)
            mma16816(acc[mi][ni], a[mi], b[ni]);
}
__device__ __forceinline__ void zero_acc(float acc[4][4][4]) {
    #pragma unroll
    for (int mi = 0; mi < 4; mi++)
        #pragma unroll
        for (int ni = 0; ni < 4; ni++)
            #pragma unroll
            for (int k = 0; k < 4; k++) acc[mi][ni][k] = 0.f;
}
__device__ __forceinline__ uint32_t ldsm_lane_off(int lane, int tile0) {
    return (uint32_t)(((tile0 + (lane & 15)) * STR + ((lane >> 4) << 3)) * 2);
}
__device__ __forceinline__ void stage_w_async(uint32_t dstBase, const u16* __restrict__ W, int tid) {
    #pragma unroll
    for (int e = tid; e < 2048; e += 256) {
        int n = e >> 4, q = e & 15;
        cp16(dstBase + (uint32_t)(n * STR + q * 8) * 2, W + n * CV + q * 8);
    }
}

// ============================================================
// prep conversions
// ============================================================
__global__ void k_cvt3(const float* __restrict__ s2, const float* __restrict__ s3,
                       const float* __restrict__ s1full,
                       u16* __restrict__ d2, u16* __restrict__ d3, u16* __restrict__ d1e)
{
    int i = blockIdx.x * 256 + threadIdx.x;
    int seg = i >> 14, j = i & 16383;
    if (seg == 0)      d2[j] = __bfloat16_as_ushort(__float2bfloat16(s2[j]));
    else if (seg == 1) d3[j] = __bfloat16_as_ushort(__float2bfloat16(s3[j]));
    else {
        int o = j >> 7, c = j & 127;
        d1e[j] = __bfloat16_as_ushort(__float2bfloat16(s1full[o * IN_DIM + CV + c]));
    }
}
__global__ void k_cvtd(const float* __restrict__ w1, const float* __restrict__ w2)
{
    int i = blockIdx.x * 256 + threadIdx.x;
    if (i < 65536) g_dw1[i] = __bfloat16_as_ushort(__float2bfloat16(w1[i]));
    else           g_dw2[i - 65536] = __bfloat16_as_ushort(__float2bfloat16(w2[i - 65536]));
}

// ============================================================
// node precompute: aS = W_self @ hV + b1 (cg=0), aN = W_nbr @ hV (cg=1)
// ============================================================
__global__ void __launch_bounds__(256, 2)
k_nodepre(const float* __restrict__ hVsrc, const float* __restrict__ w1,
          const float* __restrict__ b1, int cg)
{
    extern __shared__ char smx[];
    u16* Xs = (u16*)smx;
    u16* Ws = Xs + 128 * STR;
    const int tid = threadIdx.x;
    const int wp = tid >> 5, lane = tid & 31;
    const int wr0 = (wp & 1) * 64, wc0 = (wp >> 1) * 32;
    const int gr = lane >> 2, ck = (lane & 3) * 2;
    const int r0 = blockIdx.x * 128;
    const int koff = cg ? 2 * CV : 0;
    u16* dst = cg ? g_aN : g_aS;

    for (int e = tid; e < 128 * 32; e += 256) {
        int r = e >> 5, q = e & 31;
        float4 v = *(const float4*)&hVsrc[(r0 + r) * CV + 4 * q];
        __nv_bfloat162 a = bf2(v.x, v.y), b = bf2(v.z, v.w);
        uint2 o = { *(unsigned*)&a, *(unsigned*)&b };
        *(uint2*)&Xs[r * STR + 4 * q] = o;
    }
    for (int e = tid; e < 128 * 32; e += 256) {
        int n = e >> 5, q = e & 31;
        float4 v = *(const float4*)&w1[n * IN_DIM + koff + 4 * q];
        __nv_bfloat162 a = bf2(v.x, v.y), b = bf2(v.z, v.w);
        uint2 o = { *(unsigned*)&a, *(unsigned*)&b };
        *(uint2*)&Ws[n * STR + 4 * q] = o;
    }
    __syncthreads();
    uint32_t aA = smem_u32(Xs) + ldsm_lane_off(lane, wr0);
    uint32_t bA = smem_u32(Ws) + ldsm_lane_off(lane, wc0);
    float acc[4][4][4];
    zero_acc(acc);
    #pragma unroll
    for (int ks = 0; ks < 8; ks++)
        mma_step(aA + ks * 32, bA + ks * 32, acc);
    #pragma unroll
    for (int mi = 0; mi < 4; mi++)
        #pragma unroll
        for (int ni = 0; ni < 4; ni++) {
            int r = wr0 + mi * 16 + gr, c = wc0 + ni * 8 + ck;
            float b0v = cg ? 0.f : b1[c], b1v = cg ? 0.f : b1[c + 1];
            *(__nv_bfloat162*)&dst[(r0 + r) * CV + c] = bf2(acc[mi][ni][0] + b0v, acc[mi][ni][1] + b1v);
            *(__nv_bfloat162*)&dst[(r0 + r + 8) * CV + c] = bf2(acc[mi][ni][2] + b0v, acc[mi][ni][3] + b1v);
        }
}

// ============================================================
// k_fused2 (message): 2-layer MLP per edge; epilogue multiplies by
// mask_attend, reduces rows per node in-block, writes fp32 partials
// to g_Spart (slot = this block vs node's home block; deterministic).
// ============================================================
__global__ void __launch_bounds__(256, 2)
k_fused2(const float* __restrict__ hEf, const int* __restrict__ nbr,
         const u16* __restrict__ W1e, const u16* __restrict__ W2,
         const float* __restrict__ b2, const float* __restrict__ maskA)
{
    extern __shared__ char sm[];
    u16* B0 = (u16*)sm;                        // A (both layers)
    u16* B1 = (u16*)(sm + TBYTES);             // W1, then ma*y2 rows
    __shared__ int nbrS[128];
    __shared__ float maS[128];

    const int tid = threadIdx.x;
    const int wp = tid >> 5, lane = tid & 31;
    const int wr0 = (wp & 1) * 64, wc0 = (wp >> 1) * 32;
    const int gr = lane >> 2, ck = (lane & 3) * 2;
    const int e0 = blockIdx.x * 128;

    const uint32_t smb = smem_u32(sm);
    const uint32_t A_addr  = smb + ldsm_lane_off(lane, wr0);
    const uint32_t B1_addr = smb + TBYTES + ldsm_lane_off(lane, wc0);
    const uint32_t B2_addr = smb + 2 * TBYTES + ldsm_lane_off(lane, wc0);

    stage_w_async(smb + TBYTES, W1e, tid);
    CP_COMMIT();
    stage_w_async(smb + 2 * TBYTES, W2, tid);
    CP_COMMIT();

    // A: hE fp32 -> bf16
    #pragma unroll
    for (int e = tid; e < 128 * 16; e += 256) {
        int r = e >> 4, q = e & 15;
        const float4* src = (const float4*)&hEf[(size_t)(e0 + r) * CV + q * 8];
        float4 v0 = src[0], v1 = src[1];
        __nv_bfloat162 p0 = bf2(v0.x, v0.y), p1 = bf2(v0.z, v0.w);
        __nv_bfloat162 p2 = bf2(v1.x, v1.y), p3 = bf2(v1.z, v1.w);
        uint4 o = { *(unsigned*)&p0, *(unsigned*)&p1, *(unsigned*)&p2, *(unsigned*)&p3 };
        *(uint4*)&B0[r * STR + q * 8] = o;
    }
    if (tid < 128) { nbrS[tid] = nbr[e0 + tid]; maS[tid] = maskA[e0 + tid]; }
    CP_WAIT(1);
    __syncthreads();

    // layer 1
    float acc[4][4][4];
    zero_acc(acc);
    #pragma unroll
    for (int ks = 0; ks < 8; ks++)
        mma_step(A_addr + ks * 32, B1_addr + ks * 32, acc);
    __syncthreads();

    // epi1: gelu(acc + aS[node] + aN[nbr]) -> B0
    {
        uint32_t offS[8], offN[8];
        #pragma unroll
        for (int mi = 0; mi < 4; mi++)
            #pragma unroll
            for (int hh = 0; hh < 2; hh++) {
                int r = wr0 + mi * 16 + gr + hh * 8;
                int j = mi * 2 + hh;
                offS[j] = (uint32_t)(((e0 + r) / KNB) * CV) * 2;
                offN[j] = (uint32_t)(nbrS[r] * CV) * 2;
            }
        const char* aSb = (const char*)g_aS;
        const char* aNb = (const char*)g_aN;
        #pragma unroll
        for (int mi = 0; mi < 4; mi++)
            #pragma unroll
            for (int ni = 0; ni < 4; ni++) {
                int c = wc0 + ni * 8 + ck;
                #pragma unroll
                for (int hh = 0; hh < 2; hh++) {
                    int j = mi * 2 + hh;
                    unsigned as = *(const unsigned*)(aSb + offS[j] + c * 2);
                    unsigned an = *(const unsigned*)(aNb + offN[j] + c * 2);
                    float2 a = __bfloat1622float2(*(__nv_bfloat162*)&as);
                    float2 n = __bfloat1622float2(*(__nv_bfloat162*)&an);
                    float v0 = acc[mi][ni][2 * hh]     + a.x + n.x;
                    float v1 = acc[mi][ni][2 * hh + 1] + a.y + n.y;
                    int r = wr0 + mi * 16 + gr + hh * 8;
                    *(__nv_bfloat162*)&B0[r * STR + c] = bf2(gelu_f(v0), gelu_f(v1));
                }
            }
    }
    CP_WAIT(0);
    __syncthreads();

    // layer 2
    zero_acc(acc);
    #pragma unroll
    for (int ks = 0; ks < 8; ks++)
        mma_step(A_addr + ks * 32, B2_addr + ks * 32, acc);

    // epi2: ma * gelu(acc + b2) -> B1 (bf16 rows)
    #pragma unroll
    for (int mi = 0; mi < 4; mi++)
        #pragma unroll
        for (int ni = 0; ni < 4; ni++) {
            int r = wr0 + mi * 16 + gr, c = wc0 + ni * 8 + ck;
            float b0v = b2[c], b1v = b2[c + 1];
            float ma1 = maS[r], ma2 = maS[r + 8];
            *(__nv_bfloat162*)&B1[r * STR + c] =
                bf2(gelu_f(acc[mi][ni][0] + b0v) * ma1, gelu_f(acc[mi][ni][1] + b1v) * ma1);
            *(__nv_bfloat162*)&B1[(r + 8) * STR + c] =
                bf2(gelu_f(acc[mi][ni][2] + b0v) * ma2, gelu_f(acc[mi][ni][3] + b1v) * ma2);
        }
    __syncthreads();

    // reduce rows per node segment -> g_Spart[(n*2 + slot)*CV + c]
    {
        int nd0 = e0 / KNB;
        int ndLast = (e0 + 127) / KNB;
        int nSeg = ndLast - nd0 + 1;
        for (int sc = tid; sc < nSeg * CV; sc += 256) {
            int seg = sc >> 7, c = sc & 127;
            int n = nd0 + seg;
            int rlo = n * KNB;     if (rlo < e0) rlo = e0;
            int rhi = n * KNB + KNB; if (rhi > e0 + 128) rhi = e0 + 128;
            float s = 0.f;
            for (int r = rlo - e0; r < rhi - e0; r++)
                s += __bfloat162float(*(const __nv_bfloat16*)&B1[r * STR + c]);
            int slot = (e0 >> 7) - ((n * KNB) >> 7);
            g_Spart[((size_t)n * 2 + slot) * CV + c] = s;
        }
    }
}

// ============================================================
// k_msgfin: dh = (W3 @ S + (Σma)·b3)/30; x = hV + dh; g_v1 = LN1(x)
// ============================================================
__global__ void __launch_bounds__(256, 2)
k_msgfin(const float* __restrict__ hV, const float* __restrict__ b3,
         const float* __restrict__ lnw, const float* __restrict__ lnb,
         const float* __restrict__ maskA)
{
    extern __shared__ char smx[];
    u16* Xs = (u16*)smx;             // S tile (bf16)
    float* Zf = (float*)smx;         // overlay after GEMM
    __shared__ float smaS[128];
    const uint32_t smb = smem_u32(smx);
    const int tid = threadIdx.x;
    const int wp = tid >> 5, lane = tid & 31;
    const int wr0 = (wp & 1) * 64, wc0 = (wp >> 1) * 32;
    const int gr = lane >> 2, ck = (lane & 3) * 2;
    const int r0 = blockIdx.x * 128;

    stage_w_async(smb + TBYTES, g_w3m, tid);
    CP_COMMIT();

    // Σma per node
    {
        int r = tid >> 1, h = tid & 1;
        const float* mp = &maskA[(r0 + r) * KNB + h * 24];
        float s = 0.f;
        #pragma unroll
        for (int i = 0; i < 24; i++) s += mp[i];
        s += __shfl_xor_sync(0xffffffffu, s, 1);
        if (h == 0) smaS[r] = s;
    }

    // stage S (fp32 partials -> bf16)
    for (int e = tid; e < 128 * 32; e += 256) {
        int r = e >> 5, q = e & 31;
        int n = r0 + r;
        float4 v = *(const float4*)&g_Spart[(size_t)n * 2 * CV + 4 * q];
        if (((n * KNB) & 127) >= 81) {
            float4 w = *(const float4*)&g_Spart[((size_t)n * 2 + 1) * CV + 4 * q];
            v.x += w.x; v.y += w.y; v.z += w.z; v.w += w.w;
        }
        __nv_bfloat162 a = bf2(v.x, v.y), bb = bf2(v.z, v.w);
        uint2 o = { *(unsigned*)&a, *(unsigned*)&bb };
        *(uint2*)&Xs[r * STR + 4 * q] = o;
    }
    CP_WAIT(0);
    __syncthreads();

    uint32_t aA = smb + ldsm_lane_off(lane, wr0);
    uint32_t bA = smb + TBYTES + ldsm_lane_off(lane, wc0);
    float acc[4][4][4];
    zero_acc(acc);
    #pragma unroll
    for (int ks = 0; ks < 8; ks++)
        mma_step(aA + ks * 32, bA + ks * 32, acc);
    __syncthreads();   // before Zf overlay

    // x = hV + (acc + Σma·b3)/30 -> Zf
    #pragma unroll
    for (int mi = 0; mi < 4; mi++)
        #pragma unroll
        for (int ni = 0; ni < 4; ni++) {
            int r = wr0 + mi * 16 + gr, c = wc0 + ni * 8 + ck;
            float b0v = b3[c], b1v = b3[c + 1];
            float sm1 = smaS[r], sm2 = smaS[r + 8];
            float2 h1 = *(const float2*)&hV[(r0 + r) * CV + c];
            float2 h2 = *(const float2*)&hV[(r0 + r + 8) * CV + c];
            *(float2*)&Zf[r * Z_STR + c] = make_float2(
                h1.x + (acc[mi][ni][0] + sm1 * b0v) * (1.0f / 30.0f),
                h1.y + (acc[mi][ni][1] + sm1 * b1v) * (1.0f / 30.0f));
            *(float2*)&Zf[(r + 8) * Z_STR + c] = make_float2(
                h2.x + (acc[mi][ni][2] + sm2 * b0v) * (1.0f / 30.0f),
                h2.y + (acc[mi][ni][3] + sm2 * b1v) * (1.0f / 30.0f));
        }
    __syncthreads();
    {
        int r = tid >> 1, h = tid & 1;
        float s = 0.f, sq = 0.f;
        #pragma unroll 8
        for (int c = h * 64; c < h * 64 + 64; c++) {
            float v = Zf[r * Z_STR + c];
            s += v; sq += v * v;
        }
        s  += __shfl_xor_sync(0xffffffffu, s, 1);
        sq += __shfl_xor_sync(0xffffffffu, sq, 1);
        float mean = s * (1.0f / CV);
        float var  = sq * (1.0f / CV) - mean * mean;
        float inv  = rsqrtf(var + LN_EPS);
        for (int c = h * 64; c < h * 64 + 64; c++) {
            float v = Zf[r * Z_STR + c];
            g_v1[(r0 + r) * CV + c] = (v - mean) * inv * lnw[c] + lnb[c];
        }
    }
}

// ============================================================
// k_fused3 (edge update): 3-layer MLP + residual + LN3 -> outE
// ============================================================
__global__ void __launch_bounds__(256, 2)
k_fused3(const float* __restrict__ hEf, const int* __restrict__ nbr,
         const u16* __restrict__ W1e, const u16* __restrict__ W2, const u16* __restrict__ W3,
         const float* __restrict__ b2, const float* __restrict__ b3,
         const float* __restrict__ lnw, const float* __restrict__ lnb,
         float* __restrict__ outE)
{
    extern __shared__ char sm[];
    u16* B0 = (u16*)sm;
    float* Zf = (float*)(sm + TBYTES);
    __shared__ int nbrS[128];

    const int tid = threadIdx.x;
    const int wp = tid >> 5, lane = tid & 31;
    const int wr0 = (wp & 1) * 64, wc0 = (wp >> 1) * 32;
    const int gr = lane >> 2, ck = (lane & 3) * 2;
    const int e0 = blockIdx.x * 128;

    const uint32_t smb = smem_u32(sm);
    const uint32_t A_addr  = smb + ldsm_lane_off(lane, wr0);
    const uint32_t B1_addr = smb + TBYTES + ldsm_lane_off(lane, wc0);
    const uint32_t B2_addr = smb + 2 * TBYTES + ldsm_lane_off(lane, wc0);

    stage_w_async(smb + TBYTES, W1e, tid);
    CP_COMMIT();
    stage_w_async(smb + 2 * TBYTES, W2, tid);
    CP_COMMIT();

    #pragma unroll
    for (int e = tid; e < 128 * 16; e += 256) {
        int r = e >> 4, q = e & 15;
        const float4* src = (const float4*)&hEf[(size_t)(e0 + r) * CV + q * 8];
        float4 v0 = src[0], v1 = src[1];
        __nv_bfloat162 p0 = bf2(v0.x, v0.y), p1 = bf2(v0.z, v0.w);
        __nv_bfloat162 p2 = bf2(v1.x, v1.y), p3 = bf2(v1.z, v1.w);
        uint4 o = { *(unsigned*)&p0, *(unsigned*)&p1, *(unsigned*)&p2, *(unsigned*)&p3 };
        *(uint4*)&B0[r * STR + q * 8] = o;
    }
    if (tid < 128) nbrS[tid] = nbr[e0 + tid];
    CP_WAIT(1);
    __syncthreads();

    float acc[4][4][4];
    zero_acc(acc);
    #pragma unroll
    for (int ks = 0; ks < 8; ks++)
        mma_step(A_addr + ks * 32, B1_addr + ks * 32, acc);
    __syncthreads();

    {
        uint32_t offS[8], offN[8];
        #pragma unroll
        for (int mi = 0; mi < 4; mi++)
            #pragma unroll
            for (int hh = 0; hh < 2; hh++) {
                int r = wr0 + mi * 16 + gr + hh * 8;
                int j = mi * 2 + hh;
                offS[j] = (uint32_t)(((e0 + r) / KNB) * CV) * 2;
                offN[j] = (uint32_t)(nbrS[r] * CV) * 2;
            }
        const char* aSb = (const char*)g_aS;
        const char* aNb = (const char*)g_aN;
        #pragma unroll
        for (int mi = 0; mi < 4; mi++)
            #pragma unroll
            for (int ni = 0; ni < 4; ni++) {
                int c = wc0 + ni * 8 + ck;
                #pragma unroll
                for (int hh = 0; hh < 2; hh++) {
                    int j = mi * 2 + hh;
                    unsigned as = *(const unsigned*)(aSb + offS[j] + c * 2);
                    unsigned an = *(const unsigned*)(aNb + offN[j] + c * 2);
                    float2 a = __bfloat1622float2(*(__nv_bfloat162*)&as);
                    float2 n = __bfloat1622float2(*(__nv_bfloat162*)&an);
                    float v0 = acc[mi][ni][2 * hh]     + a.x + n.x;
                    float v1 = acc[mi][ni][2 * hh + 1] + a.y + n.y;
                    int r = wr0 + mi * 16 + gr + hh * 8;
                    *(__nv_bfloat162*)&B0[r * STR + c] = bf2(gelu_f(v0), gelu_f(v1));
                }
            }
    }
    stage_w_async(smb + TBYTES, W3, tid);
    CP_COMMIT();
    CP_WAIT(1);
    __syncthreads();

    zero_acc(acc);
    #pragma unroll
    for (int ks = 0; ks < 8; ks++)
        mma_step(A_addr + ks * 32, B2_addr + ks * 32, acc);
    __syncthreads();
    #pragma unroll
    for (int mi = 0; mi < 4; mi++)
        #pragma unroll
        for (int ni = 0; ni < 4; ni++) {
            int r = wr0 + mi * 16 + gr, c = wc0 + ni * 8 + ck;
            float b0v = b2[c], b1v = b2[c + 1];
            *(__nv_bfloat162*)&B0[r * STR + c] =
                bf2(gelu_f(acc[mi][ni][0] + b0v), gelu_f(acc[mi][ni][1] + b1v));
            *(__nv_bfloat162*)&B0[(r + 8) * STR + c] =
                bf2(gelu_f(acc[mi][ni][2] + b0v), gelu_f(acc[mi][ni][3] + b1v));
        }
    CP_WAIT(0);
    __syncthreads();

    zero_acc(acc);
    #pragma unroll
    for (int ks = 0; ks < 8; ks++)
        mma_step(A_addr + ks * 32, B1_addr + ks * 32, acc);

    __syncthreads();
    #pragma unroll
    for (int mi = 0; mi < 4; mi++)
        #pragma unroll
        for (int ni = 0; ni < 4; ni++) {
            int r = wr0 + mi * 16 + gr, c = wc0 + ni * 8 + ck;
            float b0v = b3[c], b1v = b3[c + 1];
            float2 res1 = *(const float2*)&hEf[(size_t)(e0 + r) * CV + c];
            float2 res2 = *(const float2*)&hEf[(size_t)(e0 + r + 8) * CV + c];
            *(float2*)&Zf[r * Z_STR + c] =
                make_float2(acc[mi][ni][0] + b0v + res1.x, acc[mi][ni][1] + b1v + res1.y);
            *(float2*)&Zf[(r + 8) * Z_STR + c] =
                make_float2(acc[mi][ni][2] + b0v + res2.x, acc[mi][ni][3] + b1v + res2.y);
        }
    __syncthreads();
    {
        int r = tid >> 1, h = tid & 1;
        float s = 0.f, sq = 0.f;
        #pragma unroll 8
        for (int c = h * 64; c < h * 64 + 64; c++) {
            float v = Zf[r * Z_STR + c];
            s += v; sq += v * v;
        }
        s  += __shfl_xor_sync(0xffffffffu, s, 1);
        sq += __shfl_xor_sync(0xffffffffu, sq, 1);
        float mean = s * (1.0f / CV);
        float var  = sq * (1.0f / CV) - mean * mean;
        float inv  = rsqrtf(var + LN_EPS);
        size_t eg = (size_t)(e0 + r) * CV;
        for (int c = h * 64; c < h * 64 + 64; c++) {
            float v = Zf[r * Z_STR + c];
            outE[eg + c] = (v - mean) * inv * lnw[c] + lnb[c];
        }
    }
}

// ============================================================
// dense1: g_yd = gelu(v1 @ d_w1^T + b1)
// ============================================================
__global__ void __launch_bounds__(256, 2)
k_dense1(const float* __restrict__ b)
{
    extern __shared__ char smx[];
    u16* Xs = (u16*)smx;
    const uint32_t smb = smem_u32(smx);
    const int tid = threadIdx.x;
    const int wp = tid >> 5, lane = tid & 31;
    const int wr0 = (wp & 1) * 64, wc0 = (wp >> 1) * 32;
    const int gr = lane >> 2, ck = (lane & 3) * 2;
    const int r0 = blockIdx.x * 128, c0 = blockIdx.y * 128;

    stage_w_async(smb + TBYTES, &g_dw1[c0 * CV], tid);
    CP_COMMIT();
    for (int e = tid; e < 128 * 32; e += 256) {
        int r = e >> 5, q = e & 31;
        float4 v = *(const float4*)&g_v1[(r0 + r) * CV + 4 * q];
        __nv_bfloat162 a = bf2(v.x, v.y), bb = bf2(v.z, v.w);
        uint2 o = { *(unsigned*)&a, *(unsigned*)&bb };
        *(uint2*)&Xs[r * STR + 4 * q] = o;
    }
    CP_WAIT(0);
    __syncthreads();
    uint32_t aA = smb + ldsm_lane_off(lane, wr0);
    uint32_t bA = smb + TBYTES + ldsm_lane_off(lane, wc0);
    float acc[4][4][4];
    zero_acc(acc);
    #pragma unroll
    for (int ks = 0; ks < 8; ks++)
        mma_step(aA + ks * 32, bA + ks * 32, acc);
    #pragma unroll
    for (int mi = 0; mi < 4; mi++)
        #pragma unroll
        for (int ni = 0; ni < 4; ni++) {
            int r = wr0 + mi * 16 + gr, cg = c0 + wc0 + ni * 8 + ck;
            float b0v = b[cg], b1v = b[cg + 1];
            *(__nv_bfloat162*)&g_yd[(size_t)(r0 + r) * DW + cg] =
                bf2(gelu_f(acc[mi][ni][0] + b0v), gelu_f(acc[mi][ni][1] + b1v));
            *(__nv_bfloat162*)&g_yd[(size_t)(r0 + r + 8) * DW + cg] =
                bf2(gelu_f(acc[mi][ni][2] + b0v), gelu_f(acc[mi][ni][3] + b1v));
        }
}

// ============================================================
// dense2: double-buffered; + residual + LN2 + mask -> outV
// ============================================================
__device__ __forceinline__ void d2_stage(uint32_t pairBase, int r0, int kt, int tid) {
    #pragma unroll
    for (int e = tid; e < 2048; e += 256) {
        int r = e >> 4, q = e & 15;
        cp16(pairBase + (uint32_t)(r * STR + q * 8) * 2,
             &g_yd[(size_t)(r0 + r) * DW + kt + q * 8]);
    }
    #pragma unroll
    for (int e = tid; e < 2048; e += 256) {
        int n = e >> 4, q = e & 15;
        cp16(pairBase + TBYTES + (uint32_t)(n * STR + q * 8) * 2,
             &g_dw2[n * DW + kt + q * 8]);
    }
    CP_COMMIT();
}

__global__ void __launch_bounds__(256, 1)
k_dense2(const float* __restrict__ b,
         const float* __restrict__ lnw, const float* __restrict__ lnb,
         const float* __restrict__ mask, float* __restrict__ outV)
{
    extern __shared__ char smx[];
    float* Zf = (float*)smx;
    const uint32_t smb = smem_u32(smx);
    const int tid = threadIdx.x;
    const int wp = tid >> 5, lane = tid & 31;
    const int wr0 = (wp & 1) * 64, wc0 = (wp >> 1) * 32;
    const int gr = lane >> 2, ck = (lane & 3) * 2;
    const int r0 = blockIdx.x * 128;

    float acc[4][4][4];
    zero_acc(acc);
    d2_stage(smb, r0, 0, tid);
    #pragma unroll
    for (int i = 0; i < 4; i++) {
        if (i < 3) d2_stage(smb + ((i + 1) & 1) * 2 * TBYTES, r0, (i + 1) * 128, tid);
        if (i < 3) { CP_WAIT(1); } else { CP_WAIT(0); }
        __syncthreads();
        uint32_t pb = smb + (i & 1) * 2 * TBYTES;
        uint32_t aA = pb + ldsm_lane_off(lane, wr0);
        uint32_t bA = pb + TBYTES + ldsm_lane_off(lane, wc0);
        #pragma unroll
        for (int ks = 0; ks < 8; ks++)
            mma_step(aA + ks * 32, bA + ks * 32, acc);
        __syncthreads();
    }
    #pragma unroll
    for (int mi = 0; mi < 4; mi++)
        #pragma unroll
        for (int ni = 0; ni < 4; ni++) {
            int r = wr0 + mi * 16 + gr, c = wc0 + ni * 8 + ck;
            float b0v = b[c], b1v = b[c + 1];
            float2 res1 = *(const float2*)&g_v1[(r0 + r) * CV + c];
            float2 res2 = *(const float2*)&g_v1[(r0 + r + 8) * CV + c];
            *(float2*)&Zf[r * Z_STR + c] =
                make_float2(acc[mi][ni][0] + b0v + res1.x, acc[mi][ni][1] + b1v + res1.y);
            *(float2*)&Zf[(r + 8) * Z_STR + c] =
                make_float2(acc[mi][ni][2] + b0v + res2.x, acc[mi][ni][3] + b1v + res2.y);
        }
    __syncthreads();
    {
        int r = tid >> 1, h = tid & 1;
        float s = 0.f, sq = 0.f;
        #pragma unroll 8
        for (int c = h * 64; c < h * 64 + 64; c++) {
            float v = Zf[r * Z_STR + c];
            s += v; sq += v * v;
        }
        s  += __shfl_xor_sync(0xffffffffu, s, 1);
        sq += __shfl_xor_sync(0xffffffffu, sq, 1);
        float mean = s * (1.0f / CV);
        float var  = sq * (1.0f / CV) - mean * mean;
        float inv  = rsqrtf(var + LN_EPS);
        float mk = mask[r0 + r];
        for (int c = h * 64; c < h * 64 + 64; c++) {
            float v = Zf[r * Z_STR + c];
            outV[(r0 + r) * CV + c] = ((v - mean) * inv * lnw[c] + lnb[c]) * mk;
        }
    }
}

// ============================================================
extern "C" void kernel_launch(void* const* d_in, const int* in_sizes, int n_in,
                              void* d_out, int out_size)
{
    (void)in_sizes; (void)n_in; (void)out_size;
    const float* hV    = (const float*)d_in[0];
    const float* hE    = (const float*)d_in[1];
    const int*   nbr   = (const int*)  d_in[2];
    const float* mask  = (const float*)d_in[3];
    const float* maskA = (const float*)d_in[4];
    const float* msg_w1 = (const float*)d_in[5];
    const float* msg_b1 = (const float*)d_in[6];
    const float* msg_w2 = (const float*)d_in[7];
    const float* msg_b2 = (const float*)d_in[8];
    const float* msg_w3 = (const float*)d_in[9];
    const float* msg_b3 = (const float*)d_in[10];
    const float* ln1_w  = (const float*)d_in[11];
    const float* ln1_b  = (const float*)d_in[12];
    const float* d_w1   = (const float*)d_in[13];
    const float* d_b1   = (const float*)d_in[14];
    const float* d_w2   = (const float*)d_in[15];
    const float* d_b2   = (const float*)d_in[16];
    const float* ln2_w  = (const float*)d_in[17];
    const float* ln2_b  = (const float*)d_in[18];
    const float* eu_w1  = (const float*)d_in[19];
    const float* eu_b1  = (const float*)d_in[20];
    const float* eu_w2  = (const float*)d_in[21];
    const float* eu_b2  = (const float*)d_in[22];
    const float* eu_w3  = (const float*)d_in[23];
    const float* eu_b3  = (const float*)d_in[24];
    const float* ln3_w  = (const float*)d_in[25];
    const float* ln3_b  = (const float*)d_in[26];

    float* outV = (float*)d_out;
    float* outE = outV + (size_t)N_NODES * CV;

    u16 *p_w2m, *p_w3m, *p_w2e, *p_w3e, *p_w1em, *p_w1ee;
    cudaGetSymbolAddress((void**)&p_w2m, g_w2m);
    cudaGetSymbolAddress((void**)&p_w3m, g_w3m);
    cudaGetSymbolAddress((void**)&p_w2e, g_w2e);
    cudaGetSymbolAddress((void**)&p_w3e, g_w3e);
    cudaGetSymbolAddress((void**)&p_w1em, g_w1em);
    cudaGetSymbolAddress((void**)&p_w1ee, g_w1ee);

    const int SMEM_F  = 3 * TBYTES;   // 104448
    const int SMEM_G  = 2 * TBYTES;   // 69632
    const int SMEM_D2 = 4 * TBYTES;   // 139264
    cudaFuncSetAttribute(k_fused2,  cudaFuncAttributeMaxDynamicSharedMemorySize, SMEM_F);
    cudaFuncSetAttribute(k_fused3,  cudaFuncAttributeMaxDynamicSharedMemorySize, SMEM_F);
    cudaFuncSetAttribute(k_msgfin,  cudaFuncAttributeMaxDynamicSharedMemorySize, SMEM_G);
    cudaFuncSetAttribute(k_nodepre, cudaFuncAttributeMaxDynamicSharedMemorySize, SMEM_G);
    cudaFuncSetAttribute(k_dense1,  cudaFuncAttributeMaxDynamicSharedMemorySize, SMEM_G);
    cudaFuncSetAttribute(k_dense2,  cudaFuncAttributeMaxDynamicSharedMemorySize, SMEM_D2);

    const int EGRID = EDGES / 128;  // 6144

    k_cvt3<<<192, 256>>>(msg_w2, msg_w3, msg_w1, p_w2m, p_w3m, p_w1em);   // 1
    k_cvt3<<<192, 256>>>(eu_w2,  eu_w3,  eu_w1,  p_w2e, p_w3e, p_w1ee);   // 2
    k_cvtd<<<512, 256>>>(d_w1, d_w2);                                     // 3
    k_nodepre<<<N_NODES / 128, 256, SMEM_G>>>(hV, msg_w1, msg_b1, 0);     // 4
    k_nodepre<<<N_NODES / 128, 256, SMEM_G>>>(hV, msg_w1, msg_b1, 1);     // 5
    k_fused2<<<EGRID, 256, SMEM_F>>>(hE, nbr, p_w1em, p_w2m,              // 6 <- profiled
                                     msg_b2, maskA);
    k_msgfin<<<N_NODES / 128, 256, SMEM_G>>>(hV, msg_b3, ln1_w, ln1_b, maskA);
    k_dense1<<<dim3(N_NODES / 128, 4), 256, SMEM_G>>>(d_b1);
    k_dense2<<<N_NODES / 128, 256, SMEM_D2>>>(d_b2, ln2_w, ln2_b, mask, outV);
    k_nodepre<<<N_NODES / 128, 256, SMEM_G>>>(outV, eu_w1, eu_b1, 0);
    k_nodepre<<<N_NODES / 128, 256, SMEM_G>>>(outV, eu_w1, eu_b1, 1);
    k_fused3<<<EGRID, 256, SMEM_F>>>(hE, nbr, p_w1ee, p_w2e, p_w3e,
                                     eu_b2, eu_b3, ln3_w, ln3_b, outE);
}